// round 5
// baseline (speedup 1.0000x reference)
#include <cuda_runtime.h>
#include <cuda_bf16.h>
#include <cstdint>
#include <math.h>

#define B_  2
#define T_  2048
#define C_  1024
#define H_  16
#define HD_ 64
#define NBH_ (B_*H_)     // 32
#define M_   (B_*T_)     // 4096

// Scratch (allocation-free: __device__ globals)
__device__ float g_Q[(size_t)NBH_ * T_ * HD_];
__device__ float g_K[(size_t)NBH_ * T_ * HD_];
__device__ float g_V[(size_t)NBH_ * T_ * HD_];
__device__ float g_Y[(size_t)M_ * C_];

// Pre-split bf16 operands
__device__ __nv_bfloat16 g_xhi[(size_t)M_ * C_],     g_xlo[(size_t)M_ * C_];
__device__ __nv_bfloat16 g_yhi[(size_t)M_ * C_],     g_ylo[(size_t)M_ * C_];
__device__ __nv_bfloat16 g_wahi[(size_t)3*C_ * C_],  g_walo[(size_t)3*C_ * C_]; // Wt[n][k]
__device__ __nv_bfloat16 g_wphi[(size_t)C_ * C_],    g_wplo[(size_t)C_ * C_];   // Wt[n][k]

// ---------------------------------------------------------------------------
// helpers
// ---------------------------------------------------------------------------
__device__ __forceinline__ void splitf(float x, uint16_t& h, uint16_t& l) {
    __nv_bfloat16 hb = __float2bfloat16(x);
    __nv_bfloat16 lb = __float2bfloat16(x - __bfloat162float(hb));
    h = *reinterpret_cast<uint16_t*>(&hb);
    l = *reinterpret_cast<uint16_t*>(&lb);
}

#define LDSM4(r0, r1, r2, r3, addr) \
    asm volatile("ldmatrix.sync.aligned.m8n8.x4.shared.b16 {%0,%1,%2,%3}, [%4];" \
        : "=r"(r0), "=r"(r1), "=r"(r2), "=r"(r3) : "r"(addr))

#define MMA_BF16(d, a, b) \
    asm volatile("mma.sync.aligned.m16n8k16.row.col.f32.bf16.bf16.f32 " \
        "{%0,%1,%2,%3},{%4,%5,%6,%7},{%8,%9},{%0,%1,%2,%3};" \
        : "+f"((d)[0]), "+f"((d)[1]), "+f"((d)[2]), "+f"((d)[3]) \
        : "r"((a)[0]), "r"((a)[1]), "r"((a)[2]), "r"((a)[3]), \
          "r"((b)[0]), "r"((b)[1]))

__device__ __forceinline__ void cp16(uint32_t dst, const void* src) {
    asm volatile("cp.async.cg.shared.global [%0], [%1], 16;" :: "r"(dst), "l"(src));
}
#define CP_COMMIT() asm volatile("cp.async.commit_group;")

// ---------------------------------------------------------------------------
// Converters
// ---------------------------------------------------------------------------
__global__ void __launch_bounds__(256) split_f4(const float* __restrict__ src,
                                                __nv_bfloat16* __restrict__ hi,
                                                __nv_bfloat16* __restrict__ lo) {
    const int i = blockIdx.x * 256 + threadIdx.x;
    const float4 v = ((const float4*)src)[i];
    uint16_t h[4], l[4];
    splitf(v.x, h[0], l[0]); splitf(v.y, h[1], l[1]);
    splitf(v.z, h[2], l[2]); splitf(v.w, h[3], l[3]);
    uint2 uh = make_uint2((uint32_t)h[0] | ((uint32_t)h[1] << 16),
                          (uint32_t)h[2] | ((uint32_t)h[3] << 16));
    uint2 ul = make_uint2((uint32_t)l[0] | ((uint32_t)l[1] << 16),
                          (uint32_t)l[2] | ((uint32_t)l[3] << 16));
    ((uint2*)hi)[i] = uh;
    ((uint2*)lo)[i] = ul;
}

// W[1024][NC] -> Wt_hi/lo[NC][1024] (transposed, split)
template<int NC>
__global__ void __launch_bounds__(256) split_wt(const float* __restrict__ W,
                                                __nv_bfloat16* __restrict__ th,
                                                __nv_bfloat16* __restrict__ tl) {
    __shared__ float tile[32][33];
    const int n0 = blockIdx.x * 32, k0 = blockIdx.y * 32;
    const int tx = threadIdx.x & 31, ty = threadIdx.x >> 5;   // 32 x 8
    #pragma unroll
    for (int r = ty; r < 32; r += 8)
        tile[r][tx] = W[(size_t)(k0 + r) * NC + n0 + tx];
    __syncthreads();
    #pragma unroll
    for (int r = ty; r < 32; r += 8) {
        const float v = tile[tx][r];             // = W[k0+tx][n0+r]
        uint16_t h, l;
        splitf(v, h, l);
        th[(size_t)(n0 + r) * 1024 + k0 + tx] = *(__nv_bfloat16*)&h;
        tl[(size_t)(n0 + r) * 1024 + k0 + tx] = *(__nv_bfloat16*)&l;
    }
}

// ---------------------------------------------------------------------------
// Epilogue scatter
// ---------------------------------------------------------------------------
template<int MODE>
__device__ __forceinline__ void emit(int m, int n, float val,
                                     const float* __restrict__ bias,
                                     float* __restrict__ out) {
    val += bias[n];
    if (MODE == 0) {
        const int bb = m >> 11;
        const int t  = m & 2047;
        if (n < C_) {
            const int h = n >> 6, d = n & 63;
            g_Q[(((size_t)(bb*H_ + h))*T_ + t)*HD_ + d] = val * 0.125f;
        } else if (n < 2*C_) {
            const int nn = n - C_;
            const int h = nn >> 6, d = nn & 63;
            g_K[(((size_t)(bb*H_ + h))*T_ + t)*HD_ + d] = val;
        } else {
            const int nn = n - 2*C_;
            const int h = nn >> 6, d = nn & 63;
            g_V[(((size_t)(bb*H_ + h))*T_ + t)*HD_ + d] = val;
        }
    } else {
        out[(size_t)m * C_ + n] = val;
    }
}

// ---------------------------------------------------------------------------
// Tensor-core GEMM, pre-split bf16 operands (3-term), cp.async 3-stage pipeline
//   C[M,*] = A[M,1024] @ Bt[n][k]^T + bias
// CTA 128x128, 8 warps (2x4), warp tile 64x32, k-chunk 16.
// smem stage: 4 planes (Ahi,Alo,Bhi,Blo) of [128][24] bf16 (pad-24 rows:
// verified conflict-free for ldmatrix, 16B-aligned halves for cp.async).
// ---------------------------------------------------------------------------
#define ROWP 24
#define PLANE16 (128*ROWP)                 // uint16 per plane
#define STG16   (4*PLANE16)                // uint16 per stage
static const int GEMM_SMEM = 3 * STG16 * (int)sizeof(uint16_t);  // 73728 B

template<int MODE>
__global__ void __launch_bounds__(256) gemm_bf16s(const __nv_bfloat16* __restrict__ Ahi,
                                                  const __nv_bfloat16* __restrict__ Alo,
                                                  const __nv_bfloat16* __restrict__ Bhi,
                                                  const __nv_bfloat16* __restrict__ Blo,
                                                  const float* __restrict__ bias,
                                                  float* __restrict__ out) {
    extern __shared__ __align__(16) uint16_t sm16[];
    const int tid  = threadIdx.x;
    const int lane = tid & 31, wid = tid >> 5;
    const int wm = wid >> 2, wn = wid & 3;
    const int m0 = blockIdx.y * 128, n0 = blockIdx.x * 128;

    const uint32_t sm_base = (uint32_t)__cvta_generic_to_shared(sm16);

    // loader: each thread owns (row, k-half); 4x cp.async 16B per stage
    const int row = tid >> 1;
    const int half = (tid & 1) * 8;                    // k offset in elements
    const __nv_bfloat16* pAhi = Ahi + (size_t)(m0 + row) * 1024 + half;
    const __nv_bfloat16* pAlo = Alo + (size_t)(m0 + row) * 1024 + half;
    const __nv_bfloat16* pBhi = Bhi + (size_t)(n0 + row) * 1024 + half;
    const __nv_bfloat16* pBlo = Blo + (size_t)(n0 + row) * 1024 + half;
    const uint32_t dst_off = (uint32_t)(row * ROWP + half) * 2;

    auto issue = [&](int stage, int k0) {
        const uint32_t b = sm_base + (uint32_t)stage * STG16 * 2 + dst_off;
        cp16(b + 0u * PLANE16 * 2, pAhi + k0);
        cp16(b + 1u * PLANE16 * 2, pAlo + k0);
        cp16(b + 2u * PLANE16 * 2, pBhi + k0);
        cp16(b + 3u * PLANE16 * 2, pBlo + k0);
        CP_COMMIT();
    };

    float acc[4][4][4];
    #pragma unroll
    for (int mt = 0; mt < 4; mt++)
        #pragma unroll
        for (int nt = 0; nt < 4; nt++)
            #pragma unroll
            for (int e = 0; e < 4; e++) acc[mt][nt][e] = 0.0f;

    const int lrow = lane & 15, lcol = (lane >> 4) * 8;

    issue(0, 0);
    issue(1, 16);

    for (int it = 0; it < 64; it++) {
        if (it < 63) asm volatile("cp.async.wait_group 1;");
        else         asm volatile("cp.async.wait_group 0;");
        __syncthreads();

        const int s = it - (it / 3) * 3;    // it % 3
        const uint32_t base_ah = sm_base + (uint32_t)(s * STG16 + 0 * PLANE16) * 2;
        const uint32_t base_al = sm_base + (uint32_t)(s * STG16 + 1 * PLANE16) * 2;
        const uint32_t base_bh = sm_base + (uint32_t)(s * STG16 + 2 * PLANE16) * 2;
        const uint32_t base_bl = sm_base + (uint32_t)(s * STG16 + 3 * PLANE16) * 2;

        uint32_t bhi[4][2], blo[4][2];
        #pragma unroll
        for (int j = 0; j < 2; j++) {
            const uint32_t off = (uint32_t)((wn*32 + j*16 + lrow) * ROWP + lcol) * 2;
            uint32_t r0, r1, r2, r3;
            LDSM4(r0, r1, r2, r3, base_bh + off);
            bhi[2*j][0] = r0; bhi[2*j][1] = r2;
            bhi[2*j+1][0] = r1; bhi[2*j+1][1] = r3;
            LDSM4(r0, r1, r2, r3, base_bl + off);
            blo[2*j][0] = r0; blo[2*j][1] = r2;
            blo[2*j+1][0] = r1; blo[2*j+1][1] = r3;
        }

        uint32_t af[4][4];
        #pragma unroll
        for (int mt = 0; mt < 4; mt++) {
            const uint32_t off = (uint32_t)((wm*64 + mt*16 + lrow) * ROWP + lcol) * 2;
            LDSM4(af[mt][0], af[mt][1], af[mt][2], af[mt][3], base_ah + off);
        }
        #pragma unroll
        for (int mt = 0; mt < 4; mt++)
            #pragma unroll
            for (int nt = 0; nt < 4; nt++) {
                MMA_BF16(acc[mt][nt], af[mt], bhi[nt]);   // hi*hi
                MMA_BF16(acc[mt][nt], af[mt], blo[nt]);   // hi*lo
            }
        #pragma unroll
        for (int mt = 0; mt < 4; mt++) {
            const uint32_t off = (uint32_t)((wm*64 + mt*16 + lrow) * ROWP + lcol) * 2;
            LDSM4(af[mt][0], af[mt][1], af[mt][2], af[mt][3], base_al + off);
        }
        #pragma unroll
        for (int mt = 0; mt < 4; mt++)
            #pragma unroll
            for (int nt = 0; nt < 4; nt++)
                MMA_BF16(acc[mt][nt], af[mt], bhi[nt]);   // lo*hi

        if (it + 2 < 64) {
            const int ns = (it + 2) - ((it + 2) / 3) * 3;
            issue(ns, (it + 2) * 16);
        }
    }

    const int gid = lane >> 2, tig = lane & 3;
    #pragma unroll
    for (int mt = 0; mt < 4; mt++)
        #pragma unroll
        for (int nt = 0; nt < 4; nt++) {
            const int mr = m0 + wm*64 + mt*16 + gid;
            const int nc = n0 + wn*32 + nt*8 + 2*tig;
            emit<MODE>(mr,     nc,     acc[mt][nt][0], bias, out);
            emit<MODE>(mr,     nc + 1, acc[mt][nt][1], bias, out);
            emit<MODE>(mr + 8, nc,     acc[mt][nt][2], bias, out);
            emit<MODE>(mr + 8, nc + 1, acc[mt][nt][3], bias, out);
        }
}

// ---------------------------------------------------------------------------
// Flash attention (fp32): unchanged (next round's target).
// ---------------------------------------------------------------------------
__global__ void __launch_bounds__(256) attn_kernel() {
    extern __shared__ __align__(16) float sm[];
    float* Qs = sm;                 // [128][64]
    float* Ks = Qs + 128*64;        // [64][65]
    float* Vt = Ks + 64*65;         // [64][65] transposed
    float* Ps = Vt + 64*65;         // [128][64]
    const int tid = threadIdx.x;
    const int tx = tid & 15, ty = tid >> 4;
    const int qi = gridDim.x - 1 - blockIdx.x;
    const int bh = blockIdx.y;

    const float* Qg = g_Q + ((size_t)bh * T_ + qi * 128) * HD_;
    const float* Kg = g_K + (size_t)bh * T_ * HD_;
    const float* Vg = g_V + (size_t)bh * T_ * HD_;

    #pragma unroll
    for (int it = 0; it < 8; it++) {
        const int i = tid + it * 256;
        ((float4*)Qs)[i] = ((const float4*)Qg)[i];
    }

    float m_i[8], l_i[8], O[8][4];
    #pragma unroll
    for (int i = 0; i < 8; i++) {
        m_i[i] = -1e30f; l_i[i] = 0.0f;
        #pragma unroll
        for (int j = 0; j < 4; j++) O[i][j] = 0.0f;
    }

    const int ktEnd = 2 * qi + 1;
    for (int kt = 0; kt <= ktEnd; kt++) {
        __syncthreads();
        const float* K0 = Kg + (size_t)kt * 64 * HD_;
        const float* V0 = Vg + (size_t)kt * 64 * HD_;
        #pragma unroll
        for (int it = 0; it < 4; it++) {
            const int i = tid + it * 256;
            const int r  = i >> 4;
            const int dq = (i & 15) << 2;
            const float4 kv = *(const float4*)(K0 + r * HD_ + dq);
            float* kd = Ks + r * 65 + dq;
            kd[0] = kv.x; kd[1] = kv.y; kd[2] = kv.z; kd[3] = kv.w;
            const float4 vv = *(const float4*)(V0 + r * HD_ + dq);
            Vt[(dq+0)*65 + r] = vv.x;
            Vt[(dq+1)*65 + r] = vv.y;
            Vt[(dq+2)*65 + r] = vv.z;
            Vt[(dq+3)*65 + r] = vv.w;
        }
        __syncthreads();

        float S[8][4] = {};
        #pragma unroll 4
        for (int d4 = 0; d4 < 16; d4++) {
            float b_[4][4];
            #pragma unroll
            for (int dd = 0; dd < 4; dd++)
                #pragma unroll
                for (int j = 0; j < 4; j++)
                    b_[dd][j] = Ks[(4*tx+j)*65 + d4*4 + dd];
            #pragma unroll
            for (int g = 0; g < 2; g++) {
                #pragma unroll
                for (int i = 0; i < 4; i++) {
                    float a_[4];
                    *(float4*)a_ = *(const float4*)(Qs + (g*64 + 4*ty + i)*64 + d4*4);
                    #pragma unroll
                    for (int dd = 0; dd < 4; dd++)
                        #pragma unroll
                        for (int j = 0; j < 4; j++)
                            S[g*4+i][j] = fmaf(a_[dd], b_[dd][j], S[g*4+i][j]);
                }
            }
        }

        if (kt >= 2*qi) {
            #pragma unroll
            for (int g = 0; g < 2; g++)
                #pragma unroll
                for (int i = 0; i < 4; i++)
                    #pragma unroll
                    for (int j = 0; j < 4; j++) {
                        const int r = qi*128 + g*64 + 4*ty + i;
                        const int c = kt*64 + 4*tx + j;
                        if (c > r) S[g*4+i][j] = -1e30f;
                    }
        }

        #pragma unroll
        for (int ii = 0; ii < 8; ii++) {
            float rm = fmaxf(fmaxf(S[ii][0], S[ii][1]), fmaxf(S[ii][2], S[ii][3]));
            #pragma unroll
            for (int s = 8; s >= 1; s >>= 1)
                rm = fmaxf(rm, __shfl_xor_sync(0xffffffffu, rm, s));
            const float mn = fmaxf(m_i[ii], rm);
            const float corr = __expf(m_i[ii] - mn);
            m_i[ii] = mn;
            float rs = 0.0f;
            #pragma unroll
            for (int j = 0; j < 4; j++) { S[ii][j] = __expf(S[ii][j] - mn); rs += S[ii][j]; }
            #pragma unroll
            for (int s = 8; s >= 1; s >>= 1)
                rs += __shfl_xor_sync(0xffffffffu, rs, s);
            l_i[ii] = l_i[ii] * corr + rs;
            #pragma unroll
            for (int j = 0; j < 4; j++) O[ii][j] *= corr;
        }

        #pragma unroll
        for (int g = 0; g < 2; g++)
            #pragma unroll
            for (int i = 0; i < 4; i++) {
                float4 pv = make_float4(S[g*4+i][0], S[g*4+i][1], S[g*4+i][2], S[g*4+i][3]);
                *(float4*)(Ps + (g*64 + 4*ty + i)*64 + 4*tx) = pv;
            }
        __syncthreads();

        #pragma unroll 4
        for (int k4 = 0; k4 < 16; k4++) {
            float v_[4][4];
            #pragma unroll
            for (int kk = 0; kk < 4; kk++)
                #pragma unroll
                for (int j = 0; j < 4; j++)
                    v_[kk][j] = Vt[(4*tx+j)*65 + k4*4 + kk];
            #pragma unroll
            for (int g = 0; g < 2; g++) {
                #pragma unroll
                for (int i = 0; i < 4; i++) {
                    float p_[4];
                    *(float4*)p_ = *(const float4*)(Ps + (g*64 + 4*ty + i)*64 + k4*4);
                    #pragma unroll
                    for (int kk = 0; kk < 4; kk++)
                        #pragma unroll
                        for (int j = 0; j < 4; j++)
                            O[g*4+i][j] = fmaf(p_[kk], v_[kk][j], O[g*4+i][j]);
                }
            }
        }
    }

    const int b = bh >> 4, h = bh & 15;
    #pragma unroll
    for (int g = 0; g < 2; g++)
        #pragma unroll
        for (int i = 0; i < 4; i++) {
            const int ii = g*4 + i;
            const float inv = 1.0f / l_i[ii];
            const int t = qi*128 + g*64 + 4*ty + i;
            float* yp = g_Y + ((size_t)(b * T_ + t)) * C_ + h * HD_ + 4*tx;
            #pragma unroll
            for (int j = 0; j < 4; j++) yp[j] = O[ii][j] * inv;
        }
}

static const int ATTN_SMEM = (128*64 + 64*65 + 64*65 + 128*64) * (int)sizeof(float); // 98816 B

extern "C" void kernel_launch(void* const* d_in, const int* in_sizes, int n_in,
                              void* d_out, int out_size) {
    const float* x      = (const float*)d_in[0];
    const float* W_attn = (const float*)d_in[1];
    const float* b_attn = (const float*)d_in[2];
    const float* W_proj = (const float*)d_in[3];
    const float* b_proj = (const float*)d_in[4];
    float* out = (float*)d_out;

    cudaFuncSetAttribute(gemm_bf16s<0>, cudaFuncAttributeMaxDynamicSharedMemorySize, GEMM_SMEM);
    cudaFuncSetAttribute(gemm_bf16s<1>, cudaFuncAttributeMaxDynamicSharedMemorySize, GEMM_SMEM);
    cudaFuncSetAttribute(attn_kernel,   cudaFuncAttributeMaxDynamicSharedMemorySize, ATTN_SMEM);

    __nv_bfloat16 *xhi, *xlo, *yhi, *ylo, *wahi, *walo, *wphi, *wplo;
    cudaGetSymbolAddress((void**)&xhi,  g_xhi);  cudaGetSymbolAddress((void**)&xlo,  g_xlo);
    cudaGetSymbolAddress((void**)&yhi,  g_yhi);  cudaGetSymbolAddress((void**)&ylo,  g_ylo);
    cudaGetSymbolAddress((void**)&wahi, g_wahi); cudaGetSymbolAddress((void**)&walo, g_walo);
    cudaGetSymbolAddress((void**)&wphi, g_wphi); cudaGetSymbolAddress((void**)&wplo, g_wplo);
    float* yf;
    cudaGetSymbolAddress((void**)&yf, g_Y);

    // converters
    split_f4<<<(M_*C_/4)/256, 256>>>(x, xhi, xlo);
    split_wt<3*C_><<<dim3(3*C_/32, C_/32), 256>>>(W_attn, wahi, walo);
    split_wt<C_><<<dim3(C_/32, C_/32), 256>>>(W_proj, wphi, wplo);

    // qkv
    gemm_bf16s<0><<<dim3(3*C_/128, M_/128), 256, GEMM_SMEM>>>(xhi, xlo, wahi, walo, b_attn, nullptr);
    // attention
    attn_kernel<<<dim3(T_/128, NBH_), 256, ATTN_SMEM>>>();
    // split Y, then proj
    split_f4<<<(M_*C_/4)/256, 256>>>(yf, yhi, ylo);
    gemm_bf16s<1><<<dim3(C_/128, M_/128), 256, GEMM_SMEM>>>(yhi, ylo, wphi, wplo, b_proj, out);
}

// round 6
// speedup vs baseline: 2.4238x; 2.4238x over previous
#include <cuda_runtime.h>
#include <cuda_bf16.h>
#include <cstdint>
#include <math.h>

#define B_  2
#define T_  2048
#define C_  1024
#define H_  16
#define HD_ 64
#define NBH_ (B_*H_)     // 32
#define M_   (B_*T_)     // 4096

// Scratch (allocation-free: __device__ globals)
__device__ float g_Q[(size_t)NBH_ * T_ * HD_];     // fp32, pre-scaled by 0.125
__device__ float g_Y[(size_t)M_ * C_];

// K split [bh][t][d], V split transposed [bh][d][t]
__device__ __nv_bfloat16 g_Khi[(size_t)NBH_ * T_ * HD_], g_Klo[(size_t)NBH_ * T_ * HD_];
__device__ __nv_bfloat16 g_Vthi[(size_t)NBH_ * HD_ * T_], g_Vtlo[(size_t)NBH_ * HD_ * T_];

// Pre-split bf16 GEMM operands
__device__ __nv_bfloat16 g_xhi[(size_t)M_ * C_],     g_xlo[(size_t)M_ * C_];
__device__ __nv_bfloat16 g_yhi[(size_t)M_ * C_],     g_ylo[(size_t)M_ * C_];
__device__ __nv_bfloat16 g_wahi[(size_t)3*C_ * C_],  g_walo[(size_t)3*C_ * C_]; // Wt[n][k]
__device__ __nv_bfloat16 g_wphi[(size_t)C_ * C_],    g_wplo[(size_t)C_ * C_];   // Wt[n][k]

// ---------------------------------------------------------------------------
// helpers
// ---------------------------------------------------------------------------
__device__ __forceinline__ void splitf(float x, uint16_t& h, uint16_t& l) {
    __nv_bfloat16 hb = __float2bfloat16(x);
    __nv_bfloat16 lb = __float2bfloat16(x - __bfloat162float(hb));
    h = *reinterpret_cast<uint16_t*>(&hb);
    l = *reinterpret_cast<uint16_t*>(&lb);
}
__device__ __forceinline__ void split2p(float x, float y, uint32_t& hi, uint32_t& lo) {
    uint16_t hx, lx, hy, ly;
    splitf(x, hx, lx); splitf(y, hy, ly);
    hi = (uint32_t)hx | ((uint32_t)hy << 16);
    lo = (uint32_t)lx | ((uint32_t)ly << 16);
}

#define LDSM4(r0, r1, r2, r3, addr) \
    asm volatile("ldmatrix.sync.aligned.m8n8.x4.shared.b16 {%0,%1,%2,%3}, [%4];" \
        : "=r"(r0), "=r"(r1), "=r"(r2), "=r"(r3) : "r"(addr))

#define MMA_BF16(d, a, b) \
    asm volatile("mma.sync.aligned.m16n8k16.row.col.f32.bf16.bf16.f32 " \
        "{%0,%1,%2,%3},{%4,%5,%6,%7},{%8,%9},{%0,%1,%2,%3};" \
        : "+f"((d)[0]), "+f"((d)[1]), "+f"((d)[2]), "+f"((d)[3]) \
        : "r"((a)[0]), "r"((a)[1]), "r"((a)[2]), "r"((a)[3]), \
          "r"((b)[0]), "r"((b)[1]))

__device__ __forceinline__ void cp16(uint32_t dst, const void* src) {
    asm volatile("cp.async.cg.shared.global [%0], [%1], 16;" :: "r"(dst), "l"(src));
}
#define CP_COMMIT() asm volatile("cp.async.commit_group;")

// ---------------------------------------------------------------------------
// Converters
// ---------------------------------------------------------------------------
__global__ void __launch_bounds__(256) split_f4(const float* __restrict__ src,
                                                __nv_bfloat16* __restrict__ hi,
                                                __nv_bfloat16* __restrict__ lo) {
    const int i = blockIdx.x * 256 + threadIdx.x;
    const float4 v = ((const float4*)src)[i];
    uint16_t h[4], l[4];
    splitf(v.x, h[0], l[0]); splitf(v.y, h[1], l[1]);
    splitf(v.z, h[2], l[2]); splitf(v.w, h[3], l[3]);
    uint2 uh = make_uint2((uint32_t)h[0] | ((uint32_t)h[1] << 16),
                          (uint32_t)h[2] | ((uint32_t)h[3] << 16));
    uint2 ul = make_uint2((uint32_t)l[0] | ((uint32_t)l[1] << 16),
                          (uint32_t)l[2] | ((uint32_t)l[3] << 16));
    ((uint2*)hi)[i] = uh;
    ((uint2*)lo)[i] = ul;
}

template<int NC>
__global__ void __launch_bounds__(256) split_wt(const float* __restrict__ W,
                                                __nv_bfloat16* __restrict__ th,
                                                __nv_bfloat16* __restrict__ tl) {
    __shared__ float tile[32][33];
    const int n0 = blockIdx.x * 32, k0 = blockIdx.y * 32;
    const int tx = threadIdx.x & 31, ty = threadIdx.x >> 5;
    #pragma unroll
    for (int r = ty; r < 32; r += 8)
        tile[r][tx] = W[(size_t)(k0 + r) * NC + n0 + tx];
    __syncthreads();
    #pragma unroll
    for (int r = ty; r < 32; r += 8) {
        const float v = tile[tx][r];
        uint16_t h, l;
        splitf(v, h, l);
        th[(size_t)(n0 + r) * 1024 + k0 + tx] = *(__nv_bfloat16*)&h;
        tl[(size_t)(n0 + r) * 1024 + k0 + tx] = *(__nv_bfloat16*)&l;
    }
}

// ---------------------------------------------------------------------------
// Epilogue scatter
// ---------------------------------------------------------------------------
template<int MODE>
__device__ __forceinline__ void emit(int m, int n, float val,
                                     const float* __restrict__ bias,
                                     float* __restrict__ out) {
    val += bias[n];
    if (MODE == 0) {
        const int bb = m >> 11;
        const int t  = m & 2047;
        if (n < C_) {
            const int h = n >> 6, d = n & 63;
            g_Q[(((size_t)(bb*H_ + h))*T_ + t)*HD_ + d] = val * 0.125f;
        } else if (n < 2*C_) {
            const int nn = n - C_;
            const int h = nn >> 6, d = nn & 63;
            uint16_t hh, ll;
            splitf(val, hh, ll);
            const size_t idx = (((size_t)(bb*H_ + h))*T_ + t)*HD_ + d;
            g_Khi[idx] = *(__nv_bfloat16*)&hh;
            g_Klo[idx] = *(__nv_bfloat16*)&ll;
        } else {
            const int nn = n - 2*C_;
            const int h = nn >> 6, d = nn & 63;
            uint16_t hh, ll;
            splitf(val, hh, ll);
            const size_t idx = (((size_t)(bb*H_ + h))*HD_ + d)*T_ + t;   // transposed
            g_Vthi[idx] = *(__nv_bfloat16*)&hh;
            g_Vtlo[idx] = *(__nv_bfloat16*)&ll;
        }
    } else {
        out[(size_t)m * C_ + n] = val;
    }
}

// ---------------------------------------------------------------------------
// Tensor-core GEMM (unchanged from round 5)
// ---------------------------------------------------------------------------
#define ROWP 24
#define PLANE16 (128*ROWP)
#define STG16   (4*PLANE16)
static const int GEMM_SMEM = 3 * STG16 * (int)sizeof(uint16_t);  // 73728 B

template<int MODE>
__global__ void __launch_bounds__(256) gemm_bf16s(const __nv_bfloat16* __restrict__ Ahi,
                                                  const __nv_bfloat16* __restrict__ Alo,
                                                  const __nv_bfloat16* __restrict__ Bhi,
                                                  const __nv_bfloat16* __restrict__ Blo,
                                                  const float* __restrict__ bias,
                                                  float* __restrict__ out) {
    extern __shared__ __align__(16) uint16_t sm16[];
    const int tid  = threadIdx.x;
    const int lane = tid & 31, wid = tid >> 5;
    const int wm = wid >> 2, wn = wid & 3;
    const int m0 = blockIdx.y * 128, n0 = blockIdx.x * 128;

    const uint32_t sm_base = (uint32_t)__cvta_generic_to_shared(sm16);

    const int row = tid >> 1;
    const int half = (tid & 1) * 8;
    const __nv_bfloat16* pAhi = Ahi + (size_t)(m0 + row) * 1024 + half;
    const __nv_bfloat16* pAlo = Alo + (size_t)(m0 + row) * 1024 + half;
    const __nv_bfloat16* pBhi = Bhi + (size_t)(n0 + row) * 1024 + half;
    const __nv_bfloat16* pBlo = Blo + (size_t)(n0 + row) * 1024 + half;
    const uint32_t dst_off = (uint32_t)(row * ROWP + half) * 2;

    auto issue = [&](int stage, int k0) {
        const uint32_t b = sm_base + (uint32_t)stage * STG16 * 2 + dst_off;
        cp16(b + 0u * PLANE16 * 2, pAhi + k0);
        cp16(b + 1u * PLANE16 * 2, pAlo + k0);
        cp16(b + 2u * PLANE16 * 2, pBhi + k0);
        cp16(b + 3u * PLANE16 * 2, pBlo + k0);
        CP_COMMIT();
    };

    float acc[4][4][4];
    #pragma unroll
    for (int mt = 0; mt < 4; mt++)
        #pragma unroll
        for (int nt = 0; nt < 4; nt++)
            #pragma unroll
            for (int e = 0; e < 4; e++) acc[mt][nt][e] = 0.0f;

    const int lrow = lane & 15, lcol = (lane >> 4) * 8;

    issue(0, 0);
    issue(1, 16);

    for (int it = 0; it < 64; it++) {
        if (it < 63) asm volatile("cp.async.wait_group 1;");
        else         asm volatile("cp.async.wait_group 0;");
        __syncthreads();

        const int s = it - (it / 3) * 3;
        const uint32_t base_ah = sm_base + (uint32_t)(s * STG16 + 0 * PLANE16) * 2;
        const uint32_t base_al = sm_base + (uint32_t)(s * STG16 + 1 * PLANE16) * 2;
        const uint32_t base_bh = sm_base + (uint32_t)(s * STG16 + 2 * PLANE16) * 2;
        const uint32_t base_bl = sm_base + (uint32_t)(s * STG16 + 3 * PLANE16) * 2;

        uint32_t bhi[4][2], blo[4][2];
        #pragma unroll
        for (int j = 0; j < 2; j++) {
            const uint32_t off = (uint32_t)((wn*32 + j*16 + lrow) * ROWP + lcol) * 2;
            uint32_t r0, r1, r2, r3;
            LDSM4(r0, r1, r2, r3, base_bh + off);
            bhi[2*j][0] = r0; bhi[2*j][1] = r2;
            bhi[2*j+1][0] = r1; bhi[2*j+1][1] = r3;
            LDSM4(r0, r1, r2, r3, base_bl + off);
            blo[2*j][0] = r0; blo[2*j][1] = r2;
            blo[2*j+1][0] = r1; blo[2*j+1][1] = r3;
        }

        uint32_t af[4][4];
        #pragma unroll
        for (int mt = 0; mt < 4; mt++) {
            const uint32_t off = (uint32_t)((wm*64 + mt*16 + lrow) * ROWP + lcol) * 2;
            LDSM4(af[mt][0], af[mt][1], af[mt][2], af[mt][3], base_ah + off);
        }
        #pragma unroll
        for (int mt = 0; mt < 4; mt++)
            #pragma unroll
            for (int nt = 0; nt < 4; nt++) {
                MMA_BF16(acc[mt][nt], af[mt], bhi[nt]);
                MMA_BF16(acc[mt][nt], af[mt], blo[nt]);
            }
        #pragma unroll
        for (int mt = 0; mt < 4; mt++) {
            const uint32_t off = (uint32_t)((wm*64 + mt*16 + lrow) * ROWP + lcol) * 2;
            LDSM4(af[mt][0], af[mt][1], af[mt][2], af[mt][3], base_al + off);
        }
        #pragma unroll
        for (int mt = 0; mt < 4; mt++)
            #pragma unroll
            for (int nt = 0; nt < 4; nt++)
                MMA_BF16(acc[mt][nt], af[mt], bhi[nt]);

        if (it + 2 < 64) {
            const int ns = (it + 2) - ((it + 2) / 3) * 3;
            issue(ns, (it + 2) * 16);
        }
    }

    const int gid = lane >> 2, tig = lane & 3;
    #pragma unroll
    for (int mt = 0; mt < 4; mt++)
        #pragma unroll
        for (int nt = 0; nt < 4; nt++) {
            const int mr = m0 + wm*64 + mt*16 + gid;
            const int nc = n0 + wn*32 + nt*8 + 2*tig;
            emit<MODE>(mr,     nc,     acc[mt][nt][0], bias, out);
            emit<MODE>(mr,     nc + 1, acc[mt][nt][1], bias, out);
            emit<MODE>(mr + 8, nc,     acc[mt][nt][2], bias, out);
            emit<MODE>(mr + 8, nc + 1, acc[mt][nt][3], bias, out);
        }
}

// ---------------------------------------------------------------------------
// Flash attention on tensor cores (bf16 3-term split, fp32 softmax/accum)
// grid (T/128, NBH), 256 threads = 8 warps; warp w owns q-rows [16w,16w+16).
// KV tile 64, double-buffered cp.async of pre-split K[t][d] / Vt[d][t].
// ---------------------------------------------------------------------------
#define KVP 72                                  // smem row pitch (bf16), conflict-free
#define PLA (64*KVP)                            // elements per plane
#define PLB (PLA*2)                             // bytes per plane
#define STAGEB (4*PLB)                          // bytes per stage
static const int ATTN_SMEM = 2 * STAGEB;        // 73728 B

__global__ void __launch_bounds__(256) attn_mma() {
    extern __shared__ __align__(16) uint16_t asm16[];
    const int tid  = threadIdx.x;
    const int lane = tid & 31, w = tid >> 5;
    const int gid  = lane >> 2, qc = lane & 3;
    const int lrow = lane & 15, lhalf = (lane >> 4);
    const int qi = gridDim.x - 1 - blockIdx.x;   // heavy tiles first
    const int bh = blockIdx.y;

    const uint32_t smb = (uint32_t)__cvta_generic_to_shared(asm16);

    const __nv_bfloat16* Khg = g_Khi  + (size_t)bh * T_ * HD_;
    const __nv_bfloat16* Klg = g_Klo  + (size_t)bh * T_ * HD_;
    const __nv_bfloat16* Vhg = g_Vthi + (size_t)bh * HD_ * T_;
    const __nv_bfloat16* Vlg = g_Vtlo + (size_t)bh * HD_ * T_;

    // loader: thread -> row r (0..63), chunk c4, two 16B chunks per plane
    const int lr = tid >> 2, c4 = tid & 3;
    auto issue = [&](int st, int kt) {
        const uint32_t sb = smb + (uint32_t)st * STAGEB;
        const __nv_bfloat16* kh = Khg + ((size_t)kt*64 + lr) * 64;
        const __nv_bfloat16* kl = Klg + ((size_t)kt*64 + lr) * 64;
        const __nv_bfloat16* vh = Vhg + (size_t)lr * T_ + kt*64;
        const __nv_bfloat16* vl = Vlg + (size_t)lr * T_ + kt*64;
        #pragma unroll
        for (int u = 0; u < 2; u++) {
            const int c = c4 + 4*u;
            const uint32_t d = sb + (uint32_t)(lr*KVP + c*8) * 2;
            cp16(d + 0u*PLB, kh + c*8);
            cp16(d + 1u*PLB, kl + c*8);
            cp16(d + 2u*PLB, vh + c*8);
            cp16(d + 3u*PLB, vl + c*8);
        }
        CP_COMMIT();
    };

    const int ktEnd = 2*qi + 1;
    issue(0, 0);

    // Q fragments (persistent, pre-scaled fp32 -> bf16 hi/lo split)
    uint32_t qhi[4][4], qlo[4][4];
    {
        const float* Qb = g_Q + ((size_t)bh * T_ + qi*128 + w*16) * HD_;
        #pragma unroll
        for (int ks = 0; ks < 4; ks++)
            #pragma unroll
            for (int kh = 0; kh < 2; kh++)
                #pragma unroll
                for (int h2 = 0; h2 < 2; h2++) {
                    const float2 v = *(const float2*)(Qb + (gid + 8*h2)*HD_ + ks*16 + kh*8 + 2*qc);
                    split2p(v.x, v.y, qhi[ks][h2 + 2*kh], qlo[ks][h2 + 2*kh]);
                }
    }

    float m0 = -1e30f, m1 = -1e30f, l0 = 0.0f, l1 = 0.0f;
    float oacc[8][4];
    #pragma unroll
    for (int dt = 0; dt < 8; dt++)
        #pragma unroll
        for (int e = 0; e < 4; e++) oacc[dt][e] = 0.0f;

    const int r0 = qi*128 + w*16 + gid;
    const int r1 = r0 + 8;
    // thread's fixed ldmatrix offset within a plane
    const uint32_t lbase = (uint32_t)(lrow*KVP + lhalf*8) * 2;

    for (int kt = 0; kt <= ktEnd; kt++) {
        if (kt + 1 <= ktEnd) issue((kt + 1) & 1, kt + 1);
        if (kt + 1 <= ktEnd) asm volatile("cp.async.wait_group 1;");
        else                 asm volatile("cp.async.wait_group 0;");
        __syncthreads();

        const uint32_t sb  = smb + (uint32_t)(kt & 1) * STAGEB;
        const uint32_t kbh = sb,            kbl = sb + PLB;
        const uint32_t vbh = sb + 2u*PLB,   vbl = sb + 3u*PLB;

        // ---- S = Q K^T (3-term) ----
        float sacc[8][4];
        #pragma unroll
        for (int nt = 0; nt < 8; nt++)
            #pragma unroll
            for (int e = 0; e < 4; e++) sacc[nt][e] = 0.0f;

        #pragma unroll
        for (int ks = 0; ks < 4; ks++) {
            #pragma unroll
            for (int np = 0; np < 4; np++) {
                const uint32_t off = lbase + (uint32_t)(np*16*KVP + ks*16) * 2;
                uint32_t h0, h1, h2, h3, e0, e1, e2, e3;
                LDSM4(h0, h1, h2, h3, kbh + off);
                LDSM4(e0, e1, e2, e3, kbl + off);
                uint32_t ba[2] = {h0, h2}, bb[2] = {h1, h3};
                uint32_t la[2] = {e0, e2}, lb[2] = {e1, e3};
                MMA_BF16(sacc[2*np],   qhi[ks], ba);
                MMA_BF16(sacc[2*np],   qlo[ks], ba);
                MMA_BF16(sacc[2*np],   qhi[ks], la);
                MMA_BF16(sacc[2*np+1], qhi[ks], bb);
                MMA_BF16(sacc[2*np+1], qlo[ks], bb);
                MMA_BF16(sacc[2*np+1], qhi[ks], lb);
            }
        }

        // ---- causal mask on diagonal tiles ----
        if (kt >= 2*qi) {
            #pragma unroll
            for (int nt = 0; nt < 8; nt++) {
                const int c0 = kt*64 + nt*8 + 2*qc;
                if (c0     > r0) sacc[nt][0] = -1e30f;
                if (c0 + 1 > r0) sacc[nt][1] = -1e30f;
                if (c0     > r1) sacc[nt][2] = -1e30f;
                if (c0 + 1 > r1) sacc[nt][3] = -1e30f;
            }
        }

        // ---- online softmax (rows r0, r1; quad-local reduction) ----
        float rm0 = -1e30f, rm1 = -1e30f;
        #pragma unroll
        for (int nt = 0; nt < 8; nt++) {
            rm0 = fmaxf(rm0, fmaxf(sacc[nt][0], sacc[nt][1]));
            rm1 = fmaxf(rm1, fmaxf(sacc[nt][2], sacc[nt][3]));
        }
        rm0 = fmaxf(rm0, __shfl_xor_sync(0xffffffffu, rm0, 1));
        rm0 = fmaxf(rm0, __shfl_xor_sync(0xffffffffu, rm0, 2));
        rm1 = fmaxf(rm1, __shfl_xor_sync(0xffffffffu, rm1, 1));
        rm1 = fmaxf(rm1, __shfl_xor_sync(0xffffffffu, rm1, 2));
        const float mn0 = fmaxf(m0, rm0), mn1 = fmaxf(m1, rm1);
        const float cr0 = __expf(m0 - mn0), cr1 = __expf(m1 - mn1);
        m0 = mn0; m1 = mn1;
        float s0 = 0.0f, s1 = 0.0f;
        #pragma unroll
        for (int nt = 0; nt < 8; nt++) {
            sacc[nt][0] = __expf(sacc[nt][0] - mn0); s0 += sacc[nt][0];
            sacc[nt][1] = __expf(sacc[nt][1] - mn0); s0 += sacc[nt][1];
            sacc[nt][2] = __expf(sacc[nt][2] - mn1); s1 += sacc[nt][2];
            sacc[nt][3] = __expf(sacc[nt][3] - mn1); s1 += sacc[nt][3];
        }
        s0 += __shfl_xor_sync(0xffffffffu, s0, 1);
        s0 += __shfl_xor_sync(0xffffffffu, s0, 2);
        s1 += __shfl_xor_sync(0xffffffffu, s1, 1);
        s1 += __shfl_xor_sync(0xffffffffu, s1, 2);
        l0 = l0 * cr0 + s0;
        l1 = l1 * cr1 + s1;
        #pragma unroll
        for (int dt = 0; dt < 8; dt++) {
            oacc[dt][0] *= cr0; oacc[dt][1] *= cr0;
            oacc[dt][2] *= cr1; oacc[dt][3] *= cr1;
        }

        // ---- O += P V (P frags built from sacc in registers; 3-term) ----
        #pragma unroll
        for (int kpv = 0; kpv < 4; kpv++) {
            uint32_t pahi[4], palo[4];
            split2p(sacc[2*kpv][0],   sacc[2*kpv][1],   pahi[0], palo[0]);
            split2p(sacc[2*kpv][2],   sacc[2*kpv][3],   pahi[1], palo[1]);
            split2p(sacc[2*kpv+1][0], sacc[2*kpv+1][1], pahi[2], palo[2]);
            split2p(sacc[2*kpv+1][2], sacc[2*kpv+1][3], pahi[3], palo[3]);
            #pragma unroll
            for (int np = 0; np < 4; np++) {
                const uint32_t off = lbase + (uint32_t)(np*16*KVP + kpv*16) * 2;
                uint32_t h0, h1, h2, h3, e0, e1, e2, e3;
                LDSM4(h0, h1, h2, h3, vbh + off);
                LDSM4(e0, e1, e2, e3, vbl + off);
                uint32_t va[2] = {h0, h2}, vb[2] = {h1, h3};
                uint32_t wa[2] = {e0, e2}, wb[2] = {e1, e3};
                MMA_BF16(oacc[2*np],   pahi, va);
                MMA_BF16(oacc[2*np],   palo, va);
                MMA_BF16(oacc[2*np],   pahi, wa);
                MMA_BF16(oacc[2*np+1], pahi, vb);
                MMA_BF16(oacc[2*np+1], palo, vb);
                MMA_BF16(oacc[2*np+1], pahi, wb);
            }
        }
        __syncthreads();   // stage reads complete before next overwrite
    }

    // ---- epilogue ----
    const int b = bh >> 4, h = bh & 15;
    const float inv0 = 1.0f / l0, inv1 = 1.0f / l1;
    float* y0 = g_Y + ((size_t)(b * T_ + r0)) * C_ + h * HD_;
    float* y1 = g_Y + ((size_t)(b * T_ + r1)) * C_ + h * HD_;
    #pragma unroll
    for (int dt = 0; dt < 8; dt++) {
        const int d = dt*8 + 2*qc;
        *(float2*)(y0 + d) = make_float2(oacc[dt][0] * inv0, oacc[dt][1] * inv0);
        *(float2*)(y1 + d) = make_float2(oacc[dt][2] * inv1, oacc[dt][3] * inv1);
    }
}

extern "C" void kernel_launch(void* const* d_in, const int* in_sizes, int n_in,
                              void* d_out, int out_size) {
    const float* x      = (const float*)d_in[0];
    const float* W_attn = (const float*)d_in[1];
    const float* b_attn = (const float*)d_in[2];
    const float* W_proj = (const float*)d_in[3];
    const float* b_proj = (const float*)d_in[4];
    float* out = (float*)d_out;

    cudaFuncSetAttribute(gemm_bf16s<0>, cudaFuncAttributeMaxDynamicSharedMemorySize, GEMM_SMEM);
    cudaFuncSetAttribute(gemm_bf16s<1>, cudaFuncAttributeMaxDynamicSharedMemorySize, GEMM_SMEM);
    cudaFuncSetAttribute(attn_mma,      cudaFuncAttributeMaxDynamicSharedMemorySize, ATTN_SMEM);

    __nv_bfloat16 *xhi, *xlo, *yhi, *ylo, *wahi, *walo, *wphi, *wplo;
    cudaGetSymbolAddress((void**)&xhi,  g_xhi);  cudaGetSymbolAddress((void**)&xlo,  g_xlo);
    cudaGetSymbolAddress((void**)&yhi,  g_yhi);  cudaGetSymbolAddress((void**)&ylo,  g_ylo);
    cudaGetSymbolAddress((void**)&wahi, g_wahi); cudaGetSymbolAddress((void**)&walo, g_walo);
    cudaGetSymbolAddress((void**)&wphi, g_wphi); cudaGetSymbolAddress((void**)&wplo, g_wplo);
    float* yf;
    cudaGetSymbolAddress((void**)&yf, g_Y);

    // converters
    split_f4<<<(M_*C_/4)/256, 256>>>(x, xhi, xlo);
    split_wt<3*C_><<<dim3(3*C_/32, C_/32), 256>>>(W_attn, wahi, walo);
    split_wt<C_><<<dim3(C_/32, C_/32), 256>>>(W_proj, wphi, wplo);

    // qkv (epilogue pre-splits K and transposed V)
    gemm_bf16s<0><<<dim3(3*C_/128, M_/128), 256, GEMM_SMEM>>>(xhi, xlo, wahi, walo, b_attn, nullptr);
    // attention on tensor cores
    attn_mma<<<dim3(T_/128, NBH_), 256, ATTN_SMEM>>>();
    // split Y, then proj
    split_f4<<<(M_*C_/4)/256, 256>>>(yf, yhi, ylo);
    gemm_bf16s<1><<<dim3(C_/128, M_/128), 256, GEMM_SMEM>>>(yhi, ylo, wphi, wplo, b_proj, out);
}

// round 8
// speedup vs baseline: 3.1963x; 1.3187x over previous
#include <cuda_runtime.h>
#include <cuda_fp16.h>
#include <cstdint>
#include <math.h>

#define B_  2
#define T_  2048
#define C_  1024
#define H_  16
#define HD_ 64
#define NBH_ (B_*H_)     // 32
#define M_   (B_*T_)     // 4096

// Scratch (allocation-free: __device__ globals), all fp16 operand planes
__device__ __half g_Qhi[(size_t)NBH_ * T_ * HD_], g_Qlo[(size_t)NBH_ * T_ * HD_]; // pre-scaled
__device__ __half g_Kh [(size_t)NBH_ * T_ * HD_];                                  // [bh][t][d]
__device__ __half g_Vth[(size_t)NBH_ * HD_ * T_];                                  // [bh][d][t]
__device__ __half g_xhi[(size_t)M_ * C_], g_xlo[(size_t)M_ * C_];
__device__ __half g_yhi[(size_t)M_ * C_], g_ylo[(size_t)M_ * C_];
__device__ __half g_wah[(size_t)3*C_ * C_];   // W_attn^T [n][k]
__device__ __half g_wph[(size_t)C_ * C_];     // W_proj^T [n][k]

// ---------------------------------------------------------------------------
// helpers
// ---------------------------------------------------------------------------
__device__ __forceinline__ void splith(float x, uint16_t& h, uint16_t& l) {
    __half hb = __float2half_rn(x);
    __half lb = __float2half_rn(x - __half2float(hb));
    h = *reinterpret_cast<uint16_t*>(&hb);
    l = *reinterpret_cast<uint16_t*>(&lb);
}
__device__ __forceinline__ void split2h(float x, float y, uint32_t& hi, uint32_t& lo) {
    uint16_t hx, lx, hy, ly;
    splith(x, hx, lx); splith(y, hy, ly);
    hi = (uint32_t)hx | ((uint32_t)hy << 16);
    lo = (uint32_t)lx | ((uint32_t)ly << 16);
}

#define LDSM4(r0, r1, r2, r3, addr) \
    asm volatile("ldmatrix.sync.aligned.m8n8.x4.shared.b16 {%0,%1,%2,%3}, [%4];" \
        : "=r"(r0), "=r"(r1), "=r"(r2), "=r"(r3) : "r"(addr))

#define MMA_F16(d, a, b) \
    asm volatile("mma.sync.aligned.m16n8k16.row.col.f32.f16.f16.f32 " \
        "{%0,%1,%2,%3},{%4,%5,%6,%7},{%8,%9},{%0,%1,%2,%3};" \
        : "+f"((d)[0]), "+f"((d)[1]), "+f"((d)[2]), "+f"((d)[3]) \
        : "r"((a)[0]), "r"((a)[1]), "r"((a)[2]), "r"((a)[3]), \
          "r"((b)[0]), "r"((b)[1]))

__device__ __forceinline__ void cp16(uint32_t dst, const void* src) {
    asm volatile("cp.async.cg.shared.global [%0], [%1], 16;" :: "r"(dst), "l"(src));
}
#define CP_COMMIT() asm volatile("cp.async.commit_group;")

// ---------------------------------------------------------------------------
// Converters
// ---------------------------------------------------------------------------
__global__ void __launch_bounds__(256) split_f4(const float* __restrict__ src,
                                                __half* __restrict__ hi,
                                                __half* __restrict__ lo) {
    const int i = blockIdx.x * 256 + threadIdx.x;
    const float4 v = ((const float4*)src)[i];
    uint16_t h[4], l[4];
    splith(v.x, h[0], l[0]); splith(v.y, h[1], l[1]);
    splith(v.z, h[2], l[2]); splith(v.w, h[3], l[3]);
    uint2 uh = make_uint2((uint32_t)h[0] | ((uint32_t)h[1] << 16),
                          (uint32_t)h[2] | ((uint32_t)h[3] << 16));
    uint2 ul = make_uint2((uint32_t)l[0] | ((uint32_t)l[1] << 16),
                          (uint32_t)l[2] | ((uint32_t)l[3] << 16));
    ((uint2*)hi)[i] = uh;
    ((uint2*)lo)[i] = ul;
}

// W[1024][NC] -> Wt[n][k] fp16 (rounded, single plane)
template<int NC>
__global__ void __launch_bounds__(256) round_wt(const float* __restrict__ W,
                                                __half* __restrict__ th) {
    __shared__ float tile[32][33];
    const int n0 = blockIdx.x * 32, k0 = blockIdx.y * 32;
    const int tx = threadIdx.x & 31, ty = threadIdx.x >> 5;
    #pragma unroll
    for (int r = ty; r < 32; r += 8)
        tile[r][tx] = W[(size_t)(k0 + r) * NC + n0 + tx];
    __syncthreads();
    #pragma unroll
    for (int r = ty; r < 32; r += 8)
        th[(size_t)(n0 + r) * 1024 + k0 + tx] = __float2half_rn(tile[tx][r]);
}

// ---------------------------------------------------------------------------
// Epilogue scatter
// ---------------------------------------------------------------------------
template<int MODE>
__device__ __forceinline__ void emit(int m, int n, float val,
                                     const float* __restrict__ bias,
                                     float* __restrict__ out) {
    val += bias[n];
    if (MODE == 0) {
        const int bb = m >> 11;
        const int t  = m & 2047;
        if (n < C_) {
            const int h = n >> 6, d = n & 63;
            uint16_t hh, ll;
            splith(val * 0.125f, hh, ll);
            const size_t idx = (((size_t)(bb*H_ + h))*T_ + t)*HD_ + d;
            g_Qhi[idx] = *(__half*)&hh;
            g_Qlo[idx] = *(__half*)&ll;
        } else if (n < 2*C_) {
            const int nn = n - C_;
            const int h = nn >> 6, d = nn & 63;
            g_Kh[(((size_t)(bb*H_ + h))*T_ + t)*HD_ + d] = __float2half_rn(val);
        } else {
            const int nn = n - 2*C_;
            const int h = nn >> 6, d = nn & 63;
            g_Vth[(((size_t)(bb*H_ + h))*HD_ + d)*T_ + t] = __float2half_rn(val);  // transposed
        }
    } else {
        out[(size_t)m * C_ + n] = val;
    }
}

// ---------------------------------------------------------------------------
// fp16 2-term GEMM (Markidis split: A = hi+lo, B = rounded):
//   C[M,*] = A[M,1024] @ Bt[n][k]^T + bias
// CTA 128x128, 8 warps (2x4), warp tile 64x32, k-chunk 16, 3-stage cp.async.
// smem stage: 3 planes (Ahi, Alo, Bh) of [128][24] fp16. Pad-24 verified.
// ---------------------------------------------------------------------------
#define ROWP 24
#define PLANE16 (128*ROWP)
#define STG16   (3*PLANE16)
static const int GEMM_SMEM = 3 * STG16 * (int)sizeof(uint16_t);  // 55296 B

template<int MODE>
__global__ void __launch_bounds__(256) gemm_f16s(const __half* __restrict__ Ahi,
                                                 const __half* __restrict__ Alo,
                                                 const __half* __restrict__ Bh,
                                                 const float* __restrict__ bias,
                                                 float* __restrict__ out) {
    extern __shared__ __align__(16) uint16_t sm16[];
    const int tid  = threadIdx.x;
    const int lane = tid & 31, wid = tid >> 5;
    const int wm = wid >> 2, wn = wid & 3;
    const int m0 = blockIdx.y * 128, n0 = blockIdx.x * 128;

    const uint32_t sm_base = (uint32_t)__cvta_generic_to_shared(sm16);

    const int row = tid >> 1;
    const int half = (tid & 1) * 8;
    const __half* pAhi = Ahi + (size_t)(m0 + row) * 1024 + half;
    const __half* pAlo = Alo + (size_t)(m0 + row) * 1024 + half;
    const __half* pBh  = Bh  + (size_t)(n0 + row) * 1024 + half;
    const uint32_t dst_off = (uint32_t)(row * ROWP + half) * 2;

    auto issue = [&](int stage, int k0) {
        const uint32_t b = sm_base + (uint32_t)stage * STG16 * 2 + dst_off;
        cp16(b + 0u * PLANE16 * 2, pAhi + k0);
        cp16(b + 1u * PLANE16 * 2, pAlo + k0);
        cp16(b + 2u * PLANE16 * 2, pBh + k0);
        CP_COMMIT();
    };

    float acc[4][4][4];
    #pragma unroll
    for (int mt = 0; mt < 4; mt++)
        #pragma unroll
        for (int nt = 0; nt < 4; nt++)
            #pragma unroll
            for (int e = 0; e < 4; e++) acc[mt][nt][e] = 0.0f;

    const int lrow = lane & 15, lcol = (lane >> 4) * 8;

    issue(0, 0);
    issue(1, 16);

    for (int it = 0; it < 64; it++) {
        if (it < 63) asm volatile("cp.async.wait_group 1;");
        else         asm volatile("cp.async.wait_group 0;");
        __syncthreads();

        const int s = it - (it / 3) * 3;
        const uint32_t base_ah = sm_base + (uint32_t)(s * STG16 + 0 * PLANE16) * 2;
        const uint32_t base_al = sm_base + (uint32_t)(s * STG16 + 1 * PLANE16) * 2;
        const uint32_t base_bh = sm_base + (uint32_t)(s * STG16 + 2 * PLANE16) * 2;

        uint32_t bhi[4][2];
        #pragma unroll
        for (int j = 0; j < 2; j++) {
            const uint32_t off = (uint32_t)((wn*32 + j*16 + lrow) * ROWP + lcol) * 2;
            uint32_t r0, r1, r2, r3;
            LDSM4(r0, r1, r2, r3, base_bh + off);
            bhi[2*j][0] = r0; bhi[2*j][1] = r2;
            bhi[2*j+1][0] = r1; bhi[2*j+1][1] = r3;
        }

        uint32_t af[4][4];
        #pragma unroll
        for (int mt = 0; mt < 4; mt++) {
            const uint32_t off = (uint32_t)((wm*64 + mt*16 + lrow) * ROWP + lcol) * 2;
            LDSM4(af[mt][0], af[mt][1], af[mt][2], af[mt][3], base_ah + off);
        }
        #pragma unroll
        for (int mt = 0; mt < 4; mt++)
            #pragma unroll
            for (int nt = 0; nt < 4; nt++)
                MMA_F16(acc[mt][nt], af[mt], bhi[nt]);       // hi * Bh
        #pragma unroll
        for (int mt = 0; mt < 4; mt++) {
            const uint32_t off = (uint32_t)((wm*64 + mt*16 + lrow) * ROWP + lcol) * 2;
            LDSM4(af[mt][0], af[mt][1], af[mt][2], af[mt][3], base_al + off);
        }
        #pragma unroll
        for (int mt = 0; mt < 4; mt++)
            #pragma unroll
            for (int nt = 0; nt < 4; nt++)
                MMA_F16(acc[mt][nt], af[mt], bhi[nt]);       // lo * Bh

        if (it + 2 < 64) {
            const int ns = (it + 2) - ((it + 2) / 3) * 3;
            issue(ns, (it + 2) * 16);
        }
    }

    const int gid = lane >> 2, tig = lane & 3;
    #pragma unroll
    for (int mt = 0; mt < 4; mt++)
        #pragma unroll
        for (int nt = 0; nt < 4; nt++) {
            const int mr = m0 + wm*64 + mt*16 + gid;
            const int nc = n0 + wn*32 + nt*8 + 2*tig;
            emit<MODE>(mr,     nc,     acc[mt][nt][0], bias, out);
            emit<MODE>(mr,     nc + 1, acc[mt][nt][1], bias, out);
            emit<MODE>(mr + 8, nc,     acc[mt][nt][2], bias, out);
            emit<MODE>(mr + 8, nc + 1, acc[mt][nt][3], bias, out);
        }
}

// ---------------------------------------------------------------------------
// Flash attention, fp16 2-term (Q and P split; K, V rounded):
// grid (T/128, NBH), 256 threads = 8 warps; warp w owns q-rows [16w,16w+16).
// KV tile 64, 2-stage cp.async of K[t][d] / Vt[d][t] (single fp16 planes).
// Epilogue writes Y pre-split (yhi/ylo) for the proj GEMM.
// ---------------------------------------------------------------------------
#define KVP 72
#define PLA (64*KVP)                            // fp16 elements per plane
#define PLB (PLA*2)                             // bytes per plane
#define STAGEB (2*PLB)                          // K + V planes
static const int ATTN_SMEM = 2 * STAGEB;        // 36864 B

__global__ void __launch_bounds__(256) attn_mma() {
    extern __shared__ __align__(16) uint16_t asm16[];
    const int tid  = threadIdx.x;
    const int lane = tid & 31, w = tid >> 5;
    const int gid  = lane >> 2, qc = lane & 3;
    const int lrow = lane & 15, lhalf = (lane >> 4);
    const int qi = gridDim.x - 1 - blockIdx.x;   // heavy tiles first
    const int bh = blockIdx.y;

    const uint32_t smb = (uint32_t)__cvta_generic_to_shared(asm16);

    const __half* Khg = g_Kh  + (size_t)bh * T_ * HD_;
    const __half* Vhg = g_Vth + (size_t)bh * HD_ * T_;

    const int lr = tid >> 2, c4 = tid & 3;
    auto issue = [&](int st, int kt) {
        const uint32_t sb = smb + (uint32_t)st * STAGEB;
        const __half* kh = Khg + ((size_t)kt*64 + lr) * 64;
        const __half* vh = Vhg + (size_t)lr * T_ + kt*64;
        #pragma unroll
        for (int u = 0; u < 2; u++) {
            const int c = c4 + 4*u;
            const uint32_t d = sb + (uint32_t)(lr*KVP + c*8) * 2;
            cp16(d + 0u*PLB, kh + c*8);
            cp16(d + 1u*PLB, vh + c*8);
        }
        CP_COMMIT();
    };

    const int ktEnd = 2*qi + 1;
    issue(0, 0);

    // Q fragments (persistent, pre-split fp16 loaded directly as packed pairs)
    uint32_t qhi[4][4], qlo[4][4];
    {
        const size_t qb = ((size_t)bh * T_ + qi*128 + w*16) * HD_;
        #pragma unroll
        for (int ks = 0; ks < 4; ks++)
            #pragma unroll
            for (int kh = 0; kh < 2; kh++)
                #pragma unroll
                for (int h2 = 0; h2 < 2; h2++) {
                    const size_t off = qb + (size_t)(gid + 8*h2)*HD_ + ks*16 + kh*8 + 2*qc;
                    qhi[ks][h2 + 2*kh] = *(const uint32_t*)(g_Qhi + off);
                    qlo[ks][h2 + 2*kh] = *(const uint32_t*)(g_Qlo + off);
                }
    }

    float m0 = -1e30f, m1 = -1e30f, l0 = 0.0f, l1 = 0.0f;
    float oacc[8][4];
    #pragma unroll
    for (int dt = 0; dt < 8; dt++)
        #pragma unroll
        for (int e = 0; e < 4; e++) oacc[dt][e] = 0.0f;

    const int r0 = qi*128 + w*16 + gid;
    const int r1 = r0 + 8;
    const uint32_t lbase = (uint32_t)(lrow*KVP + lhalf*8) * 2;

    for (int kt = 0; kt <= ktEnd; kt++) {
        if (kt + 1 <= ktEnd) issue((kt + 1) & 1, kt + 1);
        if (kt + 1 <= ktEnd) asm volatile("cp.async.wait_group 1;");
        else                 asm volatile("cp.async.wait_group 0;");
        __syncthreads();

        const uint32_t sb  = smb + (uint32_t)(kt & 1) * STAGEB;
        const uint32_t kbh = sb, vbh = sb + PLB;

        // ---- S = Q K^T (2-term) ----
        float sacc[8][4];
        #pragma unroll
        for (int nt = 0; nt < 8; nt++)
            #pragma unroll
            for (int e = 0; e < 4; e++) sacc[nt][e] = 0.0f;

        #pragma unroll
        for (int ks = 0; ks < 4; ks++) {
            #pragma unroll
            for (int np = 0; np < 4; np++) {
                const uint32_t off = lbase + (uint32_t)(np*16*KVP + ks*16) * 2;
                uint32_t h0, h1, h2, h3;
                LDSM4(h0, h1, h2, h3, kbh + off);
                uint32_t ba[2] = {h0, h2}, bb[2] = {h1, h3};
                MMA_F16(sacc[2*np],   qhi[ks], ba);
                MMA_F16(sacc[2*np],   qlo[ks], ba);
                MMA_F16(sacc[2*np+1], qhi[ks], bb);
                MMA_F16(sacc[2*np+1], qlo[ks], bb);
            }
        }

        // ---- causal mask on diagonal tiles ----
        if (kt >= 2*qi) {
            #pragma unroll
            for (int nt = 0; nt < 8; nt++) {
                const int c0 = kt*64 + nt*8 + 2*qc;
                if (c0     > r0) sacc[nt][0] = -1e30f;
                if (c0 + 1 > r0) sacc[nt][1] = -1e30f;
                if (c0     > r1) sacc[nt][2] = -1e30f;
                if (c0 + 1 > r1) sacc[nt][3] = -1e30f;
            }
        }

        // ---- online softmax (rows r0, r1; quad-local reduction) ----
        float rm0 = -1e30f, rm1 = -1e30f;
        #pragma unroll
        for (int nt = 0; nt < 8; nt++) {
            rm0 = fmaxf(rm0, fmaxf(sacc[nt][0], sacc[nt][1]));
            rm1 = fmaxf(rm1, fmaxf(sacc[nt][2], sacc[nt][3]));
        }
        rm0 = fmaxf(rm0, __shfl_xor_sync(0xffffffffu, rm0, 1));
        rm0 = fmaxf(rm0, __shfl_xor_sync(0xffffffffu, rm0, 2));
        rm1 = fmaxf(rm1, __shfl_xor_sync(0xffffffffu, rm1, 1));
        rm1 = fmaxf(rm1, __shfl_xor_sync(0xffffffffu, rm1, 2));
        const float mn0 = fmaxf(m0, rm0), mn1 = fmaxf(m1, rm1);
        const float cr0 = __expf(m0 - mn0), cr1 = __expf(m1 - mn1);
        m0 = mn0; m1 = mn1;
        float s0 = 0.0f, s1 = 0.0f;
        #pragma unroll
        for (int nt = 0; nt < 8; nt++) {
            sacc[nt][0] = __expf(sacc[nt][0] - mn0); s0 += sacc[nt][0];
            sacc[nt][1] = __expf(sacc[nt][1] - mn0); s0 += sacc[nt][1];
            sacc[nt][2] = __expf(sacc[nt][2] - mn1); s1 += sacc[nt][2];
            sacc[nt][3] = __expf(sacc[nt][3] - mn1); s1 += sacc[nt][3];
        }
        s0 += __shfl_xor_sync(0xffffffffu, s0, 1);
        s0 += __shfl_xor_sync(0xffffffffu, s0, 2);
        s1 += __shfl_xor_sync(0xffffffffu, s1, 1);
        s1 += __shfl_xor_sync(0xffffffffu, s1, 2);
        l0 = l0 * cr0 + s0;
        l1 = l1 * cr1 + s1;
        #pragma unroll
        for (int dt = 0; dt < 8; dt++) {
            oacc[dt][0] *= cr0; oacc[dt][1] *= cr0;
            oacc[dt][2] *= cr1; oacc[dt][3] *= cr1;
        }

        // ---- O += P V (P split in-register; V rounded; 2-term) ----
        #pragma unroll
        for (int kpv = 0; kpv < 4; kpv++) {
            uint32_t pahi[4], palo[4];
            split2h(sacc[2*kpv][0],   sacc[2*kpv][1],   pahi[0], palo[0]);
            split2h(sacc[2*kpv][2],   sacc[2*kpv][3],   pahi[1], palo[1]);
            split2h(sacc[2*kpv+1][0], sacc[2*kpv+1][1], pahi[2], palo[2]);
            split2h(sacc[2*kpv+1][2], sacc[2*kpv+1][3], pahi[3], palo[3]);
            #pragma unroll
            for (int np = 0; np < 4; np++) {
                const uint32_t off = lbase + (uint32_t)(np*16*KVP + kpv*16) * 2;
                uint32_t h0, h1, h2, h3;
                LDSM4(h0, h1, h2, h3, vbh + off);
                uint32_t va[2] = {h0, h2}, vb[2] = {h1, h3};
                MMA_F16(oacc[2*np],   pahi, va);
                MMA_F16(oacc[2*np],   palo, va);
                MMA_F16(oacc[2*np+1], pahi, vb);
                MMA_F16(oacc[2*np+1], palo, vb);
            }
        }
        __syncthreads();
    }

    // ---- epilogue: write Y pre-split for the proj GEMM ----
    const int b = bh >> 4, h = bh & 15;
    const float inv0 = 1.0f / l0, inv1 = 1.0f / l1;
    const size_t y0 = ((size_t)(b * T_ + r0)) * C_ + h * HD_;
    const size_t y1 = ((size_t)(b * T_ + r1)) * C_ + h * HD_;
    #pragma unroll
    for (int dt = 0; dt < 8; dt++) {
        const int d = dt*8 + 2*qc;
        uint32_t uh, ul;
        split2h(oacc[dt][0] * inv0, oacc[dt][1] * inv0, uh, ul);
        *(uint32_t*)(g_yhi + y0 + d) = uh;
        *(uint32_t*)(g_ylo + y0 + d) = ul;
        split2h(oacc[dt][2] * inv1, oacc[dt][3] * inv1, uh, ul);
        *(uint32_t*)(g_yhi + y1 + d) = uh;
        *(uint32_t*)(g_ylo + y1 + d) = ul;
    }
}

extern "C" void kernel_launch(void* const* d_in, const int* in_sizes, int n_in,
                              void* d_out, int out_size) {
    const float* x      = (const float*)d_in[0];
    const float* W_attn = (const float*)d_in[1];
    const float* b_attn = (const float*)d_in[2];
    const float* W_proj = (const float*)d_in[3];
    const float* b_proj = (const float*)d_in[4];
    float* out = (float*)d_out;

    cudaFuncSetAttribute(gemm_f16s<0>, cudaFuncAttributeMaxDynamicSharedMemorySize, GEMM_SMEM);
    cudaFuncSetAttribute(gemm_f16s<1>, cudaFuncAttributeMaxDynamicSharedMemorySize, GEMM_SMEM);
    cudaFuncSetAttribute(attn_mma,     cudaFuncAttributeMaxDynamicSharedMemorySize, ATTN_SMEM);

    __half *xhi, *xlo, *yhi, *ylo, *wah, *wph;
    cudaGetSymbolAddress((void**)&xhi, g_xhi); cudaGetSymbolAddress((void**)&xlo, g_xlo);
    cudaGetSymbolAddress((void**)&yhi, g_yhi); cudaGetSymbolAddress((void**)&ylo, g_ylo);
    cudaGetSymbolAddress((void**)&wah, g_wah); cudaGetSymbolAddress((void**)&wph, g_wph);

    // converters
    split_f4<<<(M_*C_/4)/256, 256>>>(x, xhi, xlo);
    round_wt<3*C_><<<dim3(3*C_/32, C_/32), 256>>>(W_attn, wah);
    round_wt<C_><<<dim3(C_/32, C_/32), 256>>>(W_proj, wph);

    // qkv (epilogue pre-splits Q, rounds K and transposed V)
    gemm_f16s<0><<<dim3(3*C_/128, M_/128), 256, GEMM_SMEM>>>(xhi, xlo, wah, b_attn, nullptr);
    // attention (epilogue pre-splits Y)
    attn_mma<<<dim3(T_/128, NBH_), 256, ATTN_SMEM>>>();
    // proj
    gemm_f16s<1><<<dim3(C_/128, M_/128), 256, GEMM_SMEM>>>(yhi, ylo, wph, b_proj, out);
}

// round 9
// speedup vs baseline: 3.3436x; 1.0461x over previous
#include <cuda_runtime.h>
#include <cuda_fp16.h>
#include <cstdint>
#include <math.h>

#define B_  2
#define T_  2048
#define C_  1024
#define H_  16
#define HD_ 64
#define NBH_ (B_*H_)     // 32
#define M_   (B_*T_)     // 4096

// Scratch (allocation-free: __device__ globals), all fp16 operand planes
__device__ __half g_Qhi[(size_t)NBH_ * T_ * HD_], g_Qlo[(size_t)NBH_ * T_ * HD_]; // pre-scaled
__device__ __half g_Kh [(size_t)NBH_ * T_ * HD_];                                  // [bh][t][d]
__device__ __half g_Vth[(size_t)NBH_ * HD_ * T_];                                  // [bh][d][t]
__device__ __half g_xhi[(size_t)M_ * C_], g_xlo[(size_t)M_ * C_];
__device__ __half g_yhi[(size_t)M_ * C_], g_ylo[(size_t)M_ * C_];
__device__ __half g_wah[(size_t)3*C_ * C_];   // W_attn^T [n][k]
__device__ __half g_wph[(size_t)C_ * C_];     // W_proj^T [n][k]

// ---------------------------------------------------------------------------
// helpers
// ---------------------------------------------------------------------------
__device__ __forceinline__ void splith(float x, uint16_t& h, uint16_t& l) {
    __half hb = __float2half_rn(x);
    __half lb = __float2half_rn(x - __half2float(hb));
    h = *reinterpret_cast<uint16_t*>(&hb);
    l = *reinterpret_cast<uint16_t*>(&lb);
}
__device__ __forceinline__ void split2h(float x, float y, uint32_t& hi, uint32_t& lo) {
    uint16_t hx, lx, hy, ly;
    splith(x, hx, lx); splith(y, hy, ly);
    hi = (uint32_t)hx | ((uint32_t)hy << 16);
    lo = (uint32_t)lx | ((uint32_t)ly << 16);
}

#define LDSM4(r0, r1, r2, r3, addr) \
    asm volatile("ldmatrix.sync.aligned.m8n8.x4.shared.b16 {%0,%1,%2,%3}, [%4];" \
        : "=r"(r0), "=r"(r1), "=r"(r2), "=r"(r3) : "r"(addr))

#define MMA_F16(d, a, b) \
    asm volatile("mma.sync.aligned.m16n8k16.row.col.f32.f16.f16.f32 " \
        "{%0,%1,%2,%3},{%4,%5,%6,%7},{%8,%9},{%0,%1,%2,%3};" \
        : "+f"((d)[0]), "+f"((d)[1]), "+f"((d)[2]), "+f"((d)[3]) \
        : "r"((a)[0]), "r"((a)[1]), "r"((a)[2]), "r"((a)[3]), \
          "r"((b)[0]), "r"((b)[1]))

__device__ __forceinline__ void cp16(uint32_t dst, const void* src) {
    asm volatile("cp.async.cg.shared.global [%0], [%1], 16;" :: "r"(dst), "l"(src));
}
#define CP_COMMIT() asm volatile("cp.async.commit_group;")

// ---------------------------------------------------------------------------
// Converters
// ---------------------------------------------------------------------------
__global__ void __launch_bounds__(256) split_f4(const float* __restrict__ src,
                                                __half* __restrict__ hi,
                                                __half* __restrict__ lo) {
    const int i = blockIdx.x * 256 + threadIdx.x;
    const float4 v = ((const float4*)src)[i];
    uint16_t h[4], l[4];
    splith(v.x, h[0], l[0]); splith(v.y, h[1], l[1]);
    splith(v.z, h[2], l[2]); splith(v.w, h[3], l[3]);
    uint2 uh = make_uint2((uint32_t)h[0] | ((uint32_t)h[1] << 16),
                          (uint32_t)h[2] | ((uint32_t)h[3] << 16));
    uint2 ul = make_uint2((uint32_t)l[0] | ((uint32_t)l[1] << 16),
                          (uint32_t)l[2] | ((uint32_t)l[3] << 16));
    ((uint2*)hi)[i] = uh;
    ((uint2*)lo)[i] = ul;
}

// W[1024][NC] -> Wt[n][k] fp16 (rounded, single plane)
template<int NC>
__global__ void __launch_bounds__(256) round_wt(const float* __restrict__ W,
                                                __half* __restrict__ th) {
    __shared__ float tile[32][33];
    const int n0 = blockIdx.x * 32, k0 = blockIdx.y * 32;
    const int tx = threadIdx.x & 31, ty = threadIdx.x >> 5;
    #pragma unroll
    for (int r = ty; r < 32; r += 8)
        tile[r][tx] = W[(size_t)(k0 + r) * NC + n0 + tx];
    __syncthreads();
    #pragma unroll
    for (int r = ty; r < 32; r += 8)
        th[(size_t)(n0 + r) * 1024 + k0 + tx] = __float2half_rn(tile[tx][r]);
}

// ---------------------------------------------------------------------------
// Epilogue scatter
// ---------------------------------------------------------------------------
template<int MODE>
__device__ __forceinline__ void emit(int m, int n, float val,
                                     const float* __restrict__ bias,
                                     float* __restrict__ out) {
    val += bias[n];
    if (MODE == 0) {
        const int bb = m >> 11;
        const int t  = m & 2047;
        if (n < C_) {
            const int h = n >> 6, d = n & 63;
            uint16_t hh, ll;
            splith(val * 0.125f, hh, ll);
            const size_t idx = (((size_t)(bb*H_ + h))*T_ + t)*HD_ + d;
            g_Qhi[idx] = *(__half*)&hh;
            g_Qlo[idx] = *(__half*)&ll;
        } else if (n < 2*C_) {
            const int nn = n - C_;
            const int h = nn >> 6, d = nn & 63;
            g_Kh[(((size_t)(bb*H_ + h))*T_ + t)*HD_ + d] = __float2half_rn(val);
        } else {
            const int nn = n - 2*C_;
            const int h = nn >> 6, d = nn & 63;
            g_Vth[(((size_t)(bb*H_ + h))*HD_ + d)*T_ + t] = __float2half_rn(val);  // transposed
        }
    } else {
        out[(size_t)m * C_ + n] = val;
    }
}

// ---------------------------------------------------------------------------
// fp16 2-term GEMM (Markidis split: A = hi+lo, B = rounded):
//   C[M,*] = A[M,1024] @ Bt[n][k]^T + bias
// CTA 128x128, 8 warps (2x4), warp tile 64x32, K-CHUNK 32, 3-stage cp.async.
// smem stage: 3 planes (Ahi, Alo, Bh) of [128][40] fp16 (pitch 80 B:
// bank rotation 20 mod 32 over 8 ldmatrix rows -> conflict-free).
// ---------------------------------------------------------------------------
#define ROWP 40
#define PLANE16 (128*ROWP)           // 5120 fp16 per plane
#define STG16   (3*PLANE16)
static const int GEMM_SMEM = 3 * STG16 * (int)sizeof(uint16_t);  // 92160 B

template<int MODE>
__global__ void __launch_bounds__(256) gemm_f16s(const __half* __restrict__ Ahi,
                                                 const __half* __restrict__ Alo,
                                                 const __half* __restrict__ Bh,
                                                 const float* __restrict__ bias,
                                                 float* __restrict__ out) {
    extern __shared__ __align__(16) uint16_t sm16[];
    const int tid  = threadIdx.x;
    const int lane = tid & 31, wid = tid >> 5;
    const int wm = wid >> 2, wn = wid & 3;
    const int m0 = blockIdx.y * 128, n0 = blockIdx.x * 128;

    const uint32_t sm_base = (uint32_t)__cvta_generic_to_shared(sm16);

    // loader: row = tid>>1, k-half = (tid&1)*16; two 16B chunks per plane
    const int row = tid >> 1;
    const int kh0 = (tid & 1) * 16;
    const __half* pAhi = Ahi + (size_t)(m0 + row) * 1024 + kh0;
    const __half* pAlo = Alo + (size_t)(m0 + row) * 1024 + kh0;
    const __half* pBh  = Bh  + (size_t)(n0 + row) * 1024 + kh0;
    const uint32_t dst_off = (uint32_t)(row * ROWP + kh0) * 2;

    auto issue = [&](int stage, int k0) {
        const uint32_t b = sm_base + (uint32_t)stage * STG16 * 2 + dst_off;
        cp16(b + 0u * PLANE16 * 2,      pAhi + k0);
        cp16(b + 0u * PLANE16 * 2 + 16, pAhi + k0 + 8);
        cp16(b + 1u * PLANE16 * 2,      pAlo + k0);
        cp16(b + 1u * PLANE16 * 2 + 16, pAlo + k0 + 8);
        cp16(b + 2u * PLANE16 * 2,      pBh + k0);
        cp16(b + 2u * PLANE16 * 2 + 16, pBh + k0 + 8);
        CP_COMMIT();
    };

    float acc[4][4][4];
    #pragma unroll
    for (int mt = 0; mt < 4; mt++)
        #pragma unroll
        for (int nt = 0; nt < 4; nt++)
            #pragma unroll
            for (int e = 0; e < 4; e++) acc[mt][nt][e] = 0.0f;

    const int lrow = lane & 15, lcol = (lane >> 4) * 8;

    issue(0, 0);
    issue(1, 32);

    for (int it = 0; it < 32; it++) {
        if (it < 31) asm volatile("cp.async.wait_group 1;");
        else         asm volatile("cp.async.wait_group 0;");
        __syncthreads();

        const int s = it - (it / 3) * 3;    // it % 3
        const uint32_t base_ah = sm_base + (uint32_t)(s * STG16 + 0 * PLANE16) * 2;
        const uint32_t base_al = sm_base + (uint32_t)(s * STG16 + 1 * PLANE16) * 2;
        const uint32_t base_bh = sm_base + (uint32_t)(s * STG16 + 2 * PLANE16) * 2;

        #pragma unroll
        for (int ks = 0; ks < 2; ks++) {
            const uint32_t ko = (uint32_t)(ks * 16 + lcol) * 2;

            uint32_t bhi[4][2];
            #pragma unroll
            for (int j = 0; j < 2; j++) {
                const uint32_t off = (uint32_t)((wn*32 + j*16 + lrow) * ROWP) * 2 + ko;
                uint32_t r0, r1, r2, r3;
                LDSM4(r0, r1, r2, r3, base_bh + off);
                bhi[2*j][0] = r0; bhi[2*j][1] = r2;
                bhi[2*j+1][0] = r1; bhi[2*j+1][1] = r3;
            }

            uint32_t af[4][4];
            #pragma unroll
            for (int mt = 0; mt < 4; mt++) {
                const uint32_t off = (uint32_t)((wm*64 + mt*16 + lrow) * ROWP) * 2 + ko;
                LDSM4(af[mt][0], af[mt][1], af[mt][2], af[mt][3], base_ah + off);
            }
            #pragma unroll
            for (int mt = 0; mt < 4; mt++)
                #pragma unroll
                for (int nt = 0; nt < 4; nt++)
                    MMA_F16(acc[mt][nt], af[mt], bhi[nt]);       // hi * Bh
            #pragma unroll
            for (int mt = 0; mt < 4; mt++) {
                const uint32_t off = (uint32_t)((wm*64 + mt*16 + lrow) * ROWP) * 2 + ko;
                LDSM4(af[mt][0], af[mt][1], af[mt][2], af[mt][3], base_al + off);
            }
            #pragma unroll
            for (int mt = 0; mt < 4; mt++)
                #pragma unroll
                for (int nt = 0; nt < 4; nt++)
                    MMA_F16(acc[mt][nt], af[mt], bhi[nt]);       // lo * Bh
        }

        if (it + 2 < 32) {
            const int ns = (it + 2) - ((it + 2) / 3) * 3;
            issue(ns, (it + 2) * 32);
        }
    }

    const int gid = lane >> 2, tig = lane & 3;
    #pragma unroll
    for (int mt = 0; mt < 4; mt++)
        #pragma unroll
        for (int nt = 0; nt < 4; nt++) {
            const int mr = m0 + wm*64 + mt*16 + gid;
            const int nc = n0 + wn*32 + nt*8 + 2*tig;
            emit<MODE>(mr,     nc,     acc[mt][nt][0], bias, out);
            emit<MODE>(mr,     nc + 1, acc[mt][nt][1], bias, out);
            emit<MODE>(mr + 8, nc,     acc[mt][nt][2], bias, out);
            emit<MODE>(mr + 8, nc + 1, acc[mt][nt][3], bias, out);
        }
}

// ---------------------------------------------------------------------------
// Flash attention, fp16 2-term; KV-STAGE 128 (two 64-halves per stage).
// grid (T/128, NBH), 256 threads = 8 warps; warp w owns q-rows [16w,16w+16).
// smem stage: K0,K1 ([kv=64][d=64]) and V0,V1 ([d=64][kv=64]), pitch 72.
// ---------------------------------------------------------------------------
#define KVP 72
#define PLH (64*KVP)                            // fp16 per half-plane
#define PLHB (PLH*2)                            // bytes per half-plane
#define STAGEB (4*PLHB)                         // K0,K1,V0,V1
static const int ATTN_SMEM = 2 * STAGEB;        // 73728 B

__global__ void __launch_bounds__(256) attn_mma() {
    extern __shared__ __align__(16) uint16_t asm16[];
    const int tid  = threadIdx.x;
    const int lane = tid & 31, w = tid >> 5;
    const int gid  = lane >> 2, qc = lane & 3;
    const int lrow = lane & 15, lhalf = (lane >> 4);
    const int qi = gridDim.x - 1 - blockIdx.x;   // heavy tiles first
    const int bh = blockIdx.y;

    const uint32_t smb = (uint32_t)__cvta_generic_to_shared(asm16);

    const __half* Khg = g_Kh  + (size_t)bh * T_ * HD_;
    const __half* Vhg = g_Vth + (size_t)bh * HD_ * T_;

    const int lr = tid >> 2, c4 = tid & 3;
    auto issue = [&](int st, int stIdx) {
        const uint32_t sb = smb + (uint32_t)st * STAGEB;
        const int kv0 = stIdx * 128;
        #pragma unroll
        for (int h = 0; h < 2; h++) {
            const __half* kh = Khg + ((size_t)(kv0 + h*64) + lr) * 64;
            const __half* vh = Vhg + (size_t)lr * T_ + kv0 + h*64;
            const uint32_t kpl = sb + (uint32_t)h * PLHB;
            const uint32_t vpl = sb + (uint32_t)(2 + h) * PLHB;
            #pragma unroll
            for (int u = 0; u < 2; u++) {
                const int c = c4 + 4*u;
                const uint32_t d = (uint32_t)(lr*KVP + c*8) * 2;
                cp16(kpl + d, kh + c*8);
                cp16(vpl + d, vh + c*8);
            }
        }
        CP_COMMIT();
    };

    issue(0, 0);

    // Q fragments (persistent, pre-split fp16 loaded directly as packed pairs)
    uint32_t qhi[4][4], qlo[4][4];
    {
        const size_t qb = ((size_t)bh * T_ + qi*128 + w*16) * HD_;
        #pragma unroll
        for (int ks = 0; ks < 4; ks++)
            #pragma unroll
            for (int kh = 0; kh < 2; kh++)
                #pragma unroll
                for (int h2 = 0; h2 < 2; h2++) {
                    const size_t off = qb + (size_t)(gid + 8*h2)*HD_ + ks*16 + kh*8 + 2*qc;
                    qhi[ks][h2 + 2*kh] = *(const uint32_t*)(g_Qhi + off);
                    qlo[ks][h2 + 2*kh] = *(const uint32_t*)(g_Qlo + off);
                }
    }

    float m0 = -1e30f, m1 = -1e30f, l0 = 0.0f, l1 = 0.0f;
    float oacc[8][4];
    #pragma unroll
    for (int dt = 0; dt < 8; dt++)
        #pragma unroll
        for (int e = 0; e < 4; e++) oacc[dt][e] = 0.0f;

    const int r0 = qi*128 + w*16 + gid;
    const int r1 = r0 + 8;
    const uint32_t lbase = (uint32_t)(lrow*KVP + lhalf*8) * 2;

    for (int st = 0; st <= qi; st++) {
        if (st + 1 <= qi) issue((st + 1) & 1, st + 1);
        if (st + 1 <= qi) asm volatile("cp.async.wait_group 1;");
        else              asm volatile("cp.async.wait_group 0;");
        __syncthreads();

        const uint32_t sb = smb + (uint32_t)(st & 1) * STAGEB;

        #pragma unroll
        for (int h = 0; h < 2; h++) {
            const int kt = 2*st + h;
            const uint32_t kbh = sb + (uint32_t)h * PLHB;
            const uint32_t vbh = sb + (uint32_t)(2 + h) * PLHB;

            // ---- S = Q K^T (2-term) ----
            float sacc[8][4];
            #pragma unroll
            for (int nt = 0; nt < 8; nt++)
                #pragma unroll
                for (int e = 0; e < 4; e++) sacc[nt][e] = 0.0f;

            #pragma unroll
            for (int ks = 0; ks < 4; ks++) {
                #pragma unroll
                for (int np = 0; np < 4; np++) {
                    const uint32_t off = lbase + (uint32_t)(np*16*KVP + ks*16) * 2;
                    uint32_t h0, h1, h2, h3;
                    LDSM4(h0, h1, h2, h3, kbh + off);
                    uint32_t ba[2] = {h0, h2}, bb[2] = {h1, h3};
                    MMA_F16(sacc[2*np],   qhi[ks], ba);
                    MMA_F16(sacc[2*np],   qlo[ks], ba);
                    MMA_F16(sacc[2*np+1], qhi[ks], bb);
                    MMA_F16(sacc[2*np+1], qlo[ks], bb);
                }
            }

            // ---- causal mask on diagonal tiles ----
            if (kt >= 2*qi) {
                #pragma unroll
                for (int nt = 0; nt < 8; nt++) {
                    const int c0 = kt*64 + nt*8 + 2*qc;
                    if (c0     > r0) sacc[nt][0] = -1e30f;
                    if (c0 + 1 > r0) sacc[nt][1] = -1e30f;
                    if (c0     > r1) sacc[nt][2] = -1e30f;
                    if (c0 + 1 > r1) sacc[nt][3] = -1e30f;
                }
            }

            // ---- online softmax (rows r0, r1; quad-local reduction) ----
            float rm0 = -1e30f, rm1 = -1e30f;
            #pragma unroll
            for (int nt = 0; nt < 8; nt++) {
                rm0 = fmaxf(rm0, fmaxf(sacc[nt][0], sacc[nt][1]));
                rm1 = fmaxf(rm1, fmaxf(sacc[nt][2], sacc[nt][3]));
            }
            rm0 = fmaxf(rm0, __shfl_xor_sync(0xffffffffu, rm0, 1));
            rm0 = fmaxf(rm0, __shfl_xor_sync(0xffffffffu, rm0, 2));
            rm1 = fmaxf(rm1, __shfl_xor_sync(0xffffffffu, rm1, 1));
            rm1 = fmaxf(rm1, __shfl_xor_sync(0xffffffffu, rm1, 2));
            const float mn0 = fmaxf(m0, rm0), mn1 = fmaxf(m1, rm1);
            const float cr0 = __expf(m0 - mn0), cr1 = __expf(m1 - mn1);
            m0 = mn0; m1 = mn1;
            float s0 = 0.0f, s1 = 0.0f;
            #pragma unroll
            for (int nt = 0; nt < 8; nt++) {
                sacc[nt][0] = __expf(sacc[nt][0] - mn0); s0 += sacc[nt][0];
                sacc[nt][1] = __expf(sacc[nt][1] - mn0); s0 += sacc[nt][1];
                sacc[nt][2] = __expf(sacc[nt][2] - mn1); s1 += sacc[nt][2];
                sacc[nt][3] = __expf(sacc[nt][3] - mn1); s1 += sacc[nt][3];
            }
            s0 += __shfl_xor_sync(0xffffffffu, s0, 1);
            s0 += __shfl_xor_sync(0xffffffffu, s0, 2);
            s1 += __shfl_xor_sync(0xffffffffu, s1, 1);
            s1 += __shfl_xor_sync(0xffffffffu, s1, 2);
            l0 = l0 * cr0 + s0;
            l1 = l1 * cr1 + s1;
            #pragma unroll
            for (int dt = 0; dt < 8; dt++) {
                oacc[dt][0] *= cr0; oacc[dt][1] *= cr0;
                oacc[dt][2] *= cr1; oacc[dt][3] *= cr1;
            }

            // ---- O += P V (P split in-register; V rounded; 2-term) ----
            #pragma unroll
            for (int kpv = 0; kpv < 4; kpv++) {
                uint32_t pahi[4], palo[4];
                split2h(sacc[2*kpv][0],   sacc[2*kpv][1],   pahi[0], palo[0]);
                split2h(sacc[2*kpv][2],   sacc[2*kpv][3],   pahi[1], palo[1]);
                split2h(sacc[2*kpv+1][0], sacc[2*kpv+1][1], pahi[2], palo[2]);
                split2h(sacc[2*kpv+1][2], sacc[2*kpv+1][3], pahi[3], palo[3]);
                #pragma unroll
                for (int np = 0; np < 4; np++) {
                    const uint32_t off = lbase + (uint32_t)(np*16*KVP + kpv*16) * 2;
                    uint32_t h0, h1, h2, h3;
                    LDSM4(h0, h1, h2, h3, vbh + off);
                    uint32_t va[2] = {h0, h2}, vb[2] = {h1, h3};
                    MMA_F16(oacc[2*np],   pahi, va);
                    MMA_F16(oacc[2*np],   palo, va);
                    MMA_F16(oacc[2*np+1], pahi, vb);
                    MMA_F16(oacc[2*np+1], palo, vb);
                }
            }
        }
        __syncthreads();   // stage reads complete before next overwrite
    }

    // ---- epilogue: write Y pre-split for the proj GEMM ----
    const int b = bh >> 4, h = bh & 15;
    const float inv0 = 1.0f / l0, inv1 = 1.0f / l1;
    const size_t y0 = ((size_t)(b * T_ + r0)) * C_ + h * HD_;
    const size_t y1 = ((size_t)(b * T_ + r1)) * C_ + h * HD_;
    #pragma unroll
    for (int dt = 0; dt < 8; dt++) {
        const int d = dt*8 + 2*qc;
        uint32_t uh, ul;
        split2h(oacc[dt][0] * inv0, oacc[dt][1] * inv0, uh, ul);
        *(uint32_t*)(g_yhi + y0 + d) = uh;
        *(uint32_t*)(g_ylo + y0 + d) = ul;
        split2h(oacc[dt][2] * inv1, oacc[dt][3] * inv1, uh, ul);
        *(uint32_t*)(g_yhi + y1 + d) = uh;
        *(uint32_t*)(g_ylo + y1 + d) = ul;
    }
}

extern "C" void kernel_launch(void* const* d_in, const int* in_sizes, int n_in,
                              void* d_out, int out_size) {
    const float* x      = (const float*)d_in[0];
    const float* W_attn = (const float*)d_in[1];
    const float* b_attn = (const float*)d_in[2];
    const float* W_proj = (const float*)d_in[3];
    const float* b_proj = (const float*)d_in[4];
    float* out = (float*)d_out;

    cudaFuncSetAttribute(gemm_f16s<0>, cudaFuncAttributeMaxDynamicSharedMemorySize, GEMM_SMEM);
    cudaFuncSetAttribute(gemm_f16s<1>, cudaFuncAttributeMaxDynamicSharedMemorySize, GEMM_SMEM);
    cudaFuncSetAttribute(attn_mma,     cudaFuncAttributeMaxDynamicSharedMemorySize, ATTN_SMEM);

    __half *xhi, *xlo, *yhi, *ylo, *wah, *wph;
    cudaGetSymbolAddress((void**)&xhi, g_xhi); cudaGetSymbolAddress((void**)&xlo, g_xlo);
    cudaGetSymbolAddress((void**)&yhi, g_yhi); cudaGetSymbolAddress((void**)&ylo, g_ylo);
    cudaGetSymbolAddress((void**)&wah, g_wah); cudaGetSymbolAddress((void**)&wph, g_wph);

    // converters
    split_f4<<<(M_*C_/4)/256, 256>>>(x, xhi, xlo);
    round_wt<3*C_><<<dim3(3*C_/32, C_/32), 256>>>(W_attn, wah);
    round_wt<C_><<<dim3(C_/32, C_/32), 256>>>(W_proj, wph);

    // qkv (epilogue pre-splits Q, rounds K and transposed V)
    gemm_f16s<0><<<dim3(3*C_/128, M_/128), 256, GEMM_SMEM>>>(xhi, xlo, wah, b_attn, nullptr);
    // attention (epilogue pre-splits Y)
    attn_mma<<<dim3(T_/128, NBH_), 256, ATTN_SMEM>>>();
    // proj
    gemm_f16s<1><<<dim3(C_/128, M_/128), 256, GEMM_SMEM>>>(yhi, ylo, wph, b_proj, out);
}

// round 10
// speedup vs baseline: 5.3686x; 1.6056x over previous
#include <cuda_runtime.h>
#include <cuda_fp16.h>
#include <cstdint>
#include <math.h>

#define B_  2
#define T_  2048
#define C_  1024
#define H_  16
#define HD_ 64
#define NBH_ (B_*H_)     // 32
#define M_   (B_*T_)     // 4096

// Scratch (allocation-free: __device__ globals), all fp16 single planes
__device__ __half g_Qh[(size_t)NBH_ * T_ * HD_];   // pre-scaled by 0.125, [bh][t][d]
__device__ __half g_Kh[(size_t)NBH_ * T_ * HD_];   // [bh][t][d]
__device__ __half g_Vth[(size_t)NBH_ * HD_ * T_];  // [bh][d][t]
__device__ __half g_xh[(size_t)M_ * C_];
__device__ __half g_yh[(size_t)M_ * C_];
__device__ __half g_wah[(size_t)3*C_ * C_];   // W_attn^T [n][k]
__device__ __half g_wph[(size_t)C_ * C_];     // W_proj^T [n][k]

// ---------------------------------------------------------------------------
// helpers
// ---------------------------------------------------------------------------
__device__ __forceinline__ uint32_t pack2h(float x, float y) {
    __half2 h = __floats2half2_rn(x, y);
    return *reinterpret_cast<uint32_t*>(&h);
}

#define LDSM4(r0, r1, r2, r3, addr) \
    asm volatile("ldmatrix.sync.aligned.m8n8.x4.shared.b16 {%0,%1,%2,%3}, [%4];" \
        : "=r"(r0), "=r"(r1), "=r"(r2), "=r"(r3) : "r"(addr))

#define MMA_F16(d, a, b) \
    asm volatile("mma.sync.aligned.m16n8k16.row.col.f32.f16.f16.f32 " \
        "{%0,%1,%2,%3},{%4,%5,%6,%7},{%8,%9},{%0,%1,%2,%3};" \
        : "+f"((d)[0]), "+f"((d)[1]), "+f"((d)[2]), "+f"((d)[3]) \
        : "r"((a)[0]), "r"((a)[1]), "r"((a)[2]), "r"((a)[3]), \
          "r"((b)[0]), "r"((b)[1]))

__device__ __forceinline__ void cp16(uint32_t dst, const void* src) {
    asm volatile("cp.async.cg.shared.global [%0], [%1], 16;" :: "r"(dst), "l"(src));
}
#define CP_COMMIT() asm volatile("cp.async.commit_group;")

// ---------------------------------------------------------------------------
// Converters
// ---------------------------------------------------------------------------
__global__ void __launch_bounds__(256) round_f4(const float* __restrict__ src,
                                                __half* __restrict__ dst) {
    const int i = blockIdx.x * 256 + threadIdx.x;
    const float4 v = ((const float4*)src)[i];
    uint2 u = make_uint2(pack2h(v.x, v.y), pack2h(v.z, v.w));
    ((uint2*)dst)[i] = u;
}

// W[1024][NC] -> Wt[n][k] fp16 (rounded)
template<int NC>
__global__ void __launch_bounds__(256) round_wt(const float* __restrict__ W,
                                                __half* __restrict__ th) {
    __shared__ float tile[32][33];
    const int n0 = blockIdx.x * 32, k0 = blockIdx.y * 32;
    const int tx = threadIdx.x & 31, ty = threadIdx.x >> 5;
    #pragma unroll
    for (int r = ty; r < 32; r += 8)
        tile[r][tx] = W[(size_t)(k0 + r) * NC + n0 + tx];
    __syncthreads();
    #pragma unroll
    for (int r = ty; r < 32; r += 8)
        th[(size_t)(n0 + r) * 1024 + k0 + tx] = __float2half_rn(tile[tx][r]);
}

// ---------------------------------------------------------------------------
// Epilogue scatter
// ---------------------------------------------------------------------------
template<int MODE>
__device__ __forceinline__ void emit(int m, int n, float val,
                                     const float* __restrict__ bias,
                                     float* __restrict__ out) {
    val += bias[n];
    if (MODE == 0) {
        const int bb = m >> 11;
        const int t  = m & 2047;
        if (n < C_) {
            const int h = n >> 6, d = n & 63;
            g_Qh[(((size_t)(bb*H_ + h))*T_ + t)*HD_ + d] = __float2half_rn(val * 0.125f);
        } else if (n < 2*C_) {
            const int nn = n - C_;
            const int h = nn >> 6, d = nn & 63;
            g_Kh[(((size_t)(bb*H_ + h))*T_ + t)*HD_ + d] = __float2half_rn(val);
        } else {
            const int nn = n - 2*C_;
            const int h = nn >> 6, d = nn & 63;
            g_Vth[(((size_t)(bb*H_ + h))*HD_ + d)*T_ + t] = __float2half_rn(val);  // transposed
        }
    } else {
        out[(size_t)m * C_ + n] = val;
    }
}

// ---------------------------------------------------------------------------
// fp16 GEMM (both operands rounded, fp32 accum):
//   C[M,*] = A[M,1024] @ Bt[n][k]^T + bias
// CTA 128x128, 8 warps (2x4), warp tile 64x32, K-chunk 32, 3-stage cp.async.
// smem stage: 2 planes (A, B) of [128][40] fp16 (pitch 80 B, conflict-free).
// ---------------------------------------------------------------------------
#define ROWP 40
#define PLANE16 (128*ROWP)           // 5120 fp16 per plane
#define STG16   (2*PLANE16)
static const int GEMM_SMEM = 3 * STG16 * (int)sizeof(uint16_t);  // 61440 B

template<int MODE>
__global__ void __launch_bounds__(256) gemm_f16(const __half* __restrict__ A,
                                                const __half* __restrict__ Bh,
                                                const float* __restrict__ bias,
                                                float* __restrict__ out) {
    extern __shared__ __align__(16) uint16_t sm16[];
    const int tid  = threadIdx.x;
    const int lane = tid & 31, wid = tid >> 5;
    const int wm = wid >> 2, wn = wid & 3;
    const int m0 = blockIdx.y * 128, n0 = blockIdx.x * 128;

    const uint32_t sm_base = (uint32_t)__cvta_generic_to_shared(sm16);

    // loader: row = tid>>1, k-half = (tid&1)*16; two 16B chunks per plane
    const int row = tid >> 1;
    const int kh0 = (tid & 1) * 16;
    const __half* pA  = A  + (size_t)(m0 + row) * 1024 + kh0;
    const __half* pBh = Bh + (size_t)(n0 + row) * 1024 + kh0;
    const uint32_t dst_off = (uint32_t)(row * ROWP + kh0) * 2;

    auto issue = [&](int stage, int k0) {
        const uint32_t b = sm_base + (uint32_t)stage * STG16 * 2 + dst_off;
        cp16(b,                            pA + k0);
        cp16(b + 16,                       pA + k0 + 8);
        cp16(b + 1u * PLANE16 * 2,         pBh + k0);
        cp16(b + 1u * PLANE16 * 2 + 16,    pBh + k0 + 8);
        CP_COMMIT();
    };

    float acc[4][4][4];
    #pragma unroll
    for (int mt = 0; mt < 4; mt++)
        #pragma unroll
        for (int nt = 0; nt < 4; nt++)
            #pragma unroll
            for (int e = 0; e < 4; e++) acc[mt][nt][e] = 0.0f;

    const int lrow = lane & 15, lcol = (lane >> 4) * 8;

    issue(0, 0);
    issue(1, 32);

    for (int it = 0; it < 32; it++) {
        if (it < 31) asm volatile("cp.async.wait_group 1;");
        else         asm volatile("cp.async.wait_group 0;");
        __syncthreads();

        const int s = it - (it / 3) * 3;    // it % 3
        const uint32_t base_a = sm_base + (uint32_t)(s * STG16) * 2;
        const uint32_t base_b = sm_base + (uint32_t)(s * STG16 + PLANE16) * 2;

        #pragma unroll
        for (int ks = 0; ks < 2; ks++) {
            const uint32_t ko = (uint32_t)(ks * 16 + lcol) * 2;

            uint32_t bhi[4][2];
            #pragma unroll
            for (int j = 0; j < 2; j++) {
                const uint32_t off = (uint32_t)((wn*32 + j*16 + lrow) * ROWP) * 2 + ko;
                uint32_t r0, r1, r2, r3;
                LDSM4(r0, r1, r2, r3, base_b + off);
                bhi[2*j][0] = r0; bhi[2*j][1] = r2;
                bhi[2*j+1][0] = r1; bhi[2*j+1][1] = r3;
            }

            uint32_t af[4][4];
            #pragma unroll
            for (int mt = 0; mt < 4; mt++) {
                const uint32_t off = (uint32_t)((wm*64 + mt*16 + lrow) * ROWP) * 2 + ko;
                LDSM4(af[mt][0], af[mt][1], af[mt][2], af[mt][3], base_a + off);
            }
            #pragma unroll
            for (int mt = 0; mt < 4; mt++)
                #pragma unroll
                for (int nt = 0; nt < 4; nt++)
                    MMA_F16(acc[mt][nt], af[mt], bhi[nt]);
        }

        if (it + 2 < 32) {
            const int ns = (it + 2) - ((it + 2) / 3) * 3;
            issue(ns, (it + 2) * 32);
        }
    }

    const int gid = lane >> 2, tig = lane & 3;
    #pragma unroll
    for (int mt = 0; mt < 4; mt++)
        #pragma unroll
        for (int nt = 0; nt < 4; nt++) {
            const int mr = m0 + wm*64 + mt*16 + gid;
            const int nc = n0 + wn*32 + nt*8 + 2*tig;
            emit<MODE>(mr,     nc,     acc[mt][nt][0], bias, out);
            emit<MODE>(mr,     nc + 1, acc[mt][nt][1], bias, out);
            emit<MODE>(mr + 8, nc,     acc[mt][nt][2], bias, out);
            emit<MODE>(mr + 8, nc + 1, acc[mt][nt][3], bias, out);
        }
}

// ---------------------------------------------------------------------------
// Flash attention, fp16 rounded operands (fp32 softmax/accum);
// KV-stage 128 (two 64-halves per stage). grid (T/128, NBH), 256 threads.
// ---------------------------------------------------------------------------
#define KVP 72
#define PLH (64*KVP)                            // fp16 per half-plane
#define PLHB (PLH*2)                            // bytes per half-plane
#define STAGEB (4*PLHB)                         // K0,K1,V0,V1
static const int ATTN_SMEM = 2 * STAGEB;        // 73728 B

__global__ void __launch_bounds__(256) attn_mma() {
    extern __shared__ __align__(16) uint16_t asm16[];
    const int tid  = threadIdx.x;
    const int lane = tid & 31, w = tid >> 5;
    const int gid  = lane >> 2, qc = lane & 3;
    const int lrow = lane & 15, lhalf = (lane >> 4);
    const int qi = gridDim.x - 1 - blockIdx.x;   // heavy tiles first
    const int bh = blockIdx.y;

    const uint32_t smb = (uint32_t)__cvta_generic_to_shared(asm16);

    const __half* Khg = g_Kh  + (size_t)bh * T_ * HD_;
    const __half* Vhg = g_Vth + (size_t)bh * HD_ * T_;

    const int lr = tid >> 2, c4 = tid & 3;
    auto issue = [&](int st, int stIdx) {
        const uint32_t sb = smb + (uint32_t)st * STAGEB;
        const int kv0 = stIdx * 128;
        #pragma unroll
        for (int h = 0; h < 2; h++) {
            const __half* kh = Khg + ((size_t)(kv0 + h*64) + lr) * 64;
            const __half* vh = Vhg + (size_t)lr * T_ + kv0 + h*64;
            const uint32_t kpl = sb + (uint32_t)h * PLHB;
            const uint32_t vpl = sb + (uint32_t)(2 + h) * PLHB;
            #pragma unroll
            for (int u = 0; u < 2; u++) {
                const int c = c4 + 4*u;
                const uint32_t d = (uint32_t)(lr*KVP + c*8) * 2;
                cp16(kpl + d, kh + c*8);
                cp16(vpl + d, vh + c*8);
            }
        }
        CP_COMMIT();
    };

    issue(0, 0);

    // Q fragments (persistent, rounded fp16 loaded directly as packed pairs)
    uint32_t qh[4][4];
    {
        const size_t qb = ((size_t)bh * T_ + qi*128 + w*16) * HD_;
        #pragma unroll
        for (int ks = 0; ks < 4; ks++)
            #pragma unroll
            for (int kh = 0; kh < 2; kh++)
                #pragma unroll
                for (int h2 = 0; h2 < 2; h2++) {
                    const size_t off = qb + (size_t)(gid + 8*h2)*HD_ + ks*16 + kh*8 + 2*qc;
                    qh[ks][h2 + 2*kh] = *(const uint32_t*)(g_Qh + off);
                }
    }

    float m0 = -1e30f, m1 = -1e30f, l0 = 0.0f, l1 = 0.0f;
    float oacc[8][4];
    #pragma unroll
    for (int dt = 0; dt < 8; dt++)
        #pragma unroll
        for (int e = 0; e < 4; e++) oacc[dt][e] = 0.0f;

    const int r0 = qi*128 + w*16 + gid;
    const int r1 = r0 + 8;
    const uint32_t lbase = (uint32_t)(lrow*KVP + lhalf*8) * 2;

    for (int st = 0; st <= qi; st++) {
        if (st + 1 <= qi) issue((st + 1) & 1, st + 1);
        if (st + 1 <= qi) asm volatile("cp.async.wait_group 1;");
        else              asm volatile("cp.async.wait_group 0;");
        __syncthreads();

        const uint32_t sb = smb + (uint32_t)(st & 1) * STAGEB;

        #pragma unroll
        for (int h = 0; h < 2; h++) {
            const int kt = 2*st + h;
            const uint32_t kbh = sb + (uint32_t)h * PLHB;
            const uint32_t vbh = sb + (uint32_t)(2 + h) * PLHB;

            // ---- S = Q K^T ----
            float sacc[8][4];
            #pragma unroll
            for (int nt = 0; nt < 8; nt++)
                #pragma unroll
                for (int e = 0; e < 4; e++) sacc[nt][e] = 0.0f;

            #pragma unroll
            for (int ks = 0; ks < 4; ks++) {
                #pragma unroll
                for (int np = 0; np < 4; np++) {
                    const uint32_t off = lbase + (uint32_t)(np*16*KVP + ks*16) * 2;
                    uint32_t h0, h1, h2, h3;
                    LDSM4(h0, h1, h2, h3, kbh + off);
                    uint32_t ba[2] = {h0, h2}, bb[2] = {h1, h3};
                    MMA_F16(sacc[2*np],   qh[ks], ba);
                    MMA_F16(sacc[2*np+1], qh[ks], bb);
                }
            }

            // ---- causal mask on diagonal tiles ----
            if (kt >= 2*qi) {
                #pragma unroll
                for (int nt = 0; nt < 8; nt++) {
                    const int c0 = kt*64 + nt*8 + 2*qc;
                    if (c0     > r0) sacc[nt][0] = -1e30f;
                    if (c0 + 1 > r0) sacc[nt][1] = -1e30f;
                    if (c0     > r1) sacc[nt][2] = -1e30f;
                    if (c0 + 1 > r1) sacc[nt][3] = -1e30f;
                }
            }

            // ---- online softmax (rows r0, r1; quad-local reduction) ----
            float rm0 = -1e30f, rm1 = -1e30f;
            #pragma unroll
            for (int nt = 0; nt < 8; nt++) {
                rm0 = fmaxf(rm0, fmaxf(sacc[nt][0], sacc[nt][1]));
                rm1 = fmaxf(rm1, fmaxf(sacc[nt][2], sacc[nt][3]));
            }
            rm0 = fmaxf(rm0, __shfl_xor_sync(0xffffffffu, rm0, 1));
            rm0 = fmaxf(rm0, __shfl_xor_sync(0xffffffffu, rm0, 2));
            rm1 = fmaxf(rm1, __shfl_xor_sync(0xffffffffu, rm1, 1));
            rm1 = fmaxf(rm1, __shfl_xor_sync(0xffffffffu, rm1, 2));
            const float mn0 = fmaxf(m0, rm0), mn1 = fmaxf(m1, rm1);
            const float cr0 = __expf(m0 - mn0), cr1 = __expf(m1 - mn1);
            m0 = mn0; m1 = mn1;
            float s0 = 0.0f, s1 = 0.0f;
            #pragma unroll
            for (int nt = 0; nt < 8; nt++) {
                sacc[nt][0] = __expf(sacc[nt][0] - mn0); s0 += sacc[nt][0];
                sacc[nt][1] = __expf(sacc[nt][1] - mn0); s0 += sacc[nt][1];
                sacc[nt][2] = __expf(sacc[nt][2] - mn1); s1 += sacc[nt][2];
                sacc[nt][3] = __expf(sacc[nt][3] - mn1); s1 += sacc[nt][3];
            }
            s0 += __shfl_xor_sync(0xffffffffu, s0, 1);
            s0 += __shfl_xor_sync(0xffffffffu, s0, 2);
            s1 += __shfl_xor_sync(0xffffffffu, s1, 1);
            s1 += __shfl_xor_sync(0xffffffffu, s1, 2);
            l0 = l0 * cr0 + s0;
            l1 = l1 * cr1 + s1;
            #pragma unroll
            for (int dt = 0; dt < 8; dt++) {
                oacc[dt][0] *= cr0; oacc[dt][1] *= cr0;
                oacc[dt][2] *= cr1; oacc[dt][3] *= cr1;
            }

            // ---- O += P V (P rounded in-register) ----
            #pragma unroll
            for (int kpv = 0; kpv < 4; kpv++) {
                uint32_t pa[4];
                pa[0] = pack2h(sacc[2*kpv][0],   sacc[2*kpv][1]);
                pa[1] = pack2h(sacc[2*kpv][2],   sacc[2*kpv][3]);
                pa[2] = pack2h(sacc[2*kpv+1][0], sacc[2*kpv+1][1]);
                pa[3] = pack2h(sacc[2*kpv+1][2], sacc[2*kpv+1][3]);
                #pragma unroll
                for (int np = 0; np < 4; np++) {
                    const uint32_t off = lbase + (uint32_t)(np*16*KVP + kpv*16) * 2;
                    uint32_t h0, h1, h2, h3;
                    LDSM4(h0, h1, h2, h3, vbh + off);
                    uint32_t va[2] = {h0, h2}, vb[2] = {h1, h3};
                    MMA_F16(oacc[2*np],   pa, va);
                    MMA_F16(oacc[2*np+1], pa, vb);
                }
            }
        }
        __syncthreads();   // stage reads complete before next overwrite
    }

    // ---- epilogue: write Y rounded for the proj GEMM ----
    const int b = bh >> 4, h = bh & 15;
    const float inv0 = 1.0f / l0, inv1 = 1.0f / l1;
    const size_t y0 = ((size_t)(b * T_ + r0)) * C_ + h * HD_;
    const size_t y1 = ((size_t)(b * T_ + r1)) * C_ + h * HD_;
    #pragma unroll
    for (int dt = 0; dt < 8; dt++) {
        const int d = dt*8 + 2*qc;
        *(uint32_t*)(g_yh + y0 + d) = pack2h(oacc[dt][0] * inv0, oacc[dt][1] * inv0);
        *(uint32_t*)(g_yh + y1 + d) = pack2h(oacc[dt][2] * inv1, oacc[dt][3] * inv1);
    }
}

extern "C" void kernel_launch(void* const* d_in, const int* in_sizes, int n_in,
                              void* d_out, int out_size) {
    const float* x      = (const float*)d_in[0];
    const float* W_attn = (const float*)d_in[1];
    const float* b_attn = (const float*)d_in[2];
    const float* W_proj = (const float*)d_in[3];
    const float* b_proj = (const float*)d_in[4];
    float* out = (float*)d_out;

    cudaFuncSetAttribute(gemm_f16<0>, cudaFuncAttributeMaxDynamicSharedMemorySize, GEMM_SMEM);
    cudaFuncSetAttribute(gemm_f16<1>, cudaFuncAttributeMaxDynamicSharedMemorySize, GEMM_SMEM);
    cudaFuncSetAttribute(attn_mma,    cudaFuncAttributeMaxDynamicSharedMemorySize, ATTN_SMEM);

    __half *xh, *yh, *wah, *wph;
    cudaGetSymbolAddress((void**)&xh,  g_xh);  cudaGetSymbolAddress((void**)&yh,  g_yh);
    cudaGetSymbolAddress((void**)&wah, g_wah); cudaGetSymbolAddress((void**)&wph, g_wph);

    // converters
    round_f4<<<(M_*C_/4)/256, 256>>>(x, xh);
    round_wt<3*C_><<<dim3(3*C_/32, C_/32), 256>>>(W_attn, wah);
    round_wt<C_><<<dim3(C_/32, C_/32), 256>>>(W_proj, wph);

    // qkv (epilogue rounds Q (pre-scaled), K, transposed V)
    gemm_f16<0><<<dim3(3*C_/128, M_/128), 256, GEMM_SMEM>>>(xh, wah, b_attn, nullptr);
    // attention (epilogue rounds Y)
    attn_mma<<<dim3(T_/128, NBH_), 256, ATTN_SMEM>>>();
    // proj
    gemm_f16<1><<<dim3(C_/128, M_/128), 256, GEMM_SMEM>>>(yh, wph, b_proj, out);
}

// round 11
// speedup vs baseline: 5.6405x; 1.0506x over previous
#include <cuda_runtime.h>
#include <cuda_fp16.h>
#include <cstdint>
#include <math.h>

#define B_  2
#define T_  2048
#define C_  1024
#define H_  16
#define HD_ 64
#define NBH_ (B_*H_)     // 32
#define M_   (B_*T_)     // 4096

// Scratch (allocation-free: __device__ globals), all fp16 single planes
__device__ __half g_Qh[(size_t)NBH_ * T_ * HD_];   // pre-scaled by 0.125, [bh][t][d]
__device__ __half g_Kh[(size_t)NBH_ * T_ * HD_];   // [bh][t][d]
__device__ __half g_Vth[(size_t)NBH_ * HD_ * T_];  // [bh][d][t]
__device__ __half g_xh[(size_t)M_ * C_];
__device__ __half g_yh[(size_t)M_ * C_];
__device__ __half g_wah[(size_t)3*C_ * C_];   // W_attn^T [n][k]
__device__ __half g_wph[(size_t)C_ * C_];     // W_proj^T [n][k]

// ---------------------------------------------------------------------------
// helpers
// ---------------------------------------------------------------------------
__device__ __forceinline__ uint32_t pack2h(float x, float y) {
    __half2 h = __floats2half2_rn(x, y);
    return *reinterpret_cast<uint32_t*>(&h);
}

#define LDSM4(r0, r1, r2, r3, addr) \
    asm volatile("ldmatrix.sync.aligned.m8n8.x4.shared.b16 {%0,%1,%2,%3}, [%4];" \
        : "=r"(r0), "=r"(r1), "=r"(r2), "=r"(r3) : "r"(addr))

#define MMA_F16(d, a, b) \
    asm volatile("mma.sync.aligned.m16n8k16.row.col.f32.f16.f16.f32 " \
        "{%0,%1,%2,%3},{%4,%5,%6,%7},{%8,%9},{%0,%1,%2,%3};" \
        : "+f"((d)[0]), "+f"((d)[1]), "+f"((d)[2]), "+f"((d)[3]) \
        : "r"((a)[0]), "r"((a)[1]), "r"((a)[2]), "r"((a)[3]), \
          "r"((b)[0]), "r"((b)[1]))

__device__ __forceinline__ void cp16(uint32_t dst, const void* src) {
    asm volatile("cp.async.cg.shared.global [%0], [%1], 16;" :: "r"(dst), "l"(src));
}
#define CP_COMMIT() asm volatile("cp.async.commit_group;")

// ---------------------------------------------------------------------------
// Converters
// ---------------------------------------------------------------------------
__global__ void __launch_bounds__(256) round_f4(const float* __restrict__ src,
                                                __half* __restrict__ dst) {
    const int i = blockIdx.x * 256 + threadIdx.x;
    const float4 v = ((const float4*)src)[i];
    uint2 u = make_uint2(pack2h(v.x, v.y), pack2h(v.z, v.w));
    ((uint2*)dst)[i] = u;
}

// W[1024][NC] -> Wt[n][k] fp16 (rounded)
template<int NC>
__global__ void __launch_bounds__(256) round_wt(const float* __restrict__ W,
                                                __half* __restrict__ th) {
    __shared__ float tile[32][33];
    const int n0 = blockIdx.x * 32, k0 = blockIdx.y * 32;
    const int tx = threadIdx.x & 31, ty = threadIdx.x >> 5;
    #pragma unroll
    for (int r = ty; r < 32; r += 8)
        tile[r][tx] = W[(size_t)(k0 + r) * NC + n0 + tx];
    __syncthreads();
    #pragma unroll
    for (int r = ty; r < 32; r += 8)
        th[(size_t)(n0 + r) * 1024 + k0 + tx] = __float2half_rn(tile[tx][r]);
}

// ---------------------------------------------------------------------------
// Epilogue scatter
// ---------------------------------------------------------------------------
template<int MODE>
__device__ __forceinline__ void emit(int m, int n, float val,
                                     const float* __restrict__ bias,
                                     float* __restrict__ out) {
    val += bias[n];
    if (MODE == 0) {
        const int bb = m >> 11;
        const int t  = m & 2047;
        if (n < C_) {
            const int h = n >> 6, d = n & 63;
            g_Qh[(((size_t)(bb*H_ + h))*T_ + t)*HD_ + d] = __float2half_rn(val * 0.125f);
        } else if (n < 2*C_) {
            const int nn = n - C_;
            const int h = nn >> 6, d = nn & 63;
            g_Kh[(((size_t)(bb*H_ + h))*T_ + t)*HD_ + d] = __float2half_rn(val);
        } else {
            const int nn = n - 2*C_;
            const int h = nn >> 6, d = nn & 63;
            g_Vth[(((size_t)(bb*H_ + h))*HD_ + d)*T_ + t] = __float2half_rn(val);  // transposed
        }
    } else {
        out[(size_t)m * C_ + n] = val;
    }
}

// ---------------------------------------------------------------------------
// fp16 GEMM (both operands rounded, fp32 accum):
//   C[M,*] = A[M,1024] @ Bt[n][k]^T + bias
// CTA 128x64, 256 threads, 8 warps (4m x 2n), warp tile 32x32,
// K-chunk 32, 3-stage cp.async. smem stage: A [128][40] + B [64][40] fp16.
// 32 accs/thread -> ~60 regs -> 4 CTAs/SM (occ ~50%).
// ---------------------------------------------------------------------------
#define ROWP 40
#define PLANEA (128*ROWP)            // 5120 fp16
#define PLANEB (64*ROWP)             // 2560 fp16
#define STG16  (PLANEA+PLANEB)       // 7680 fp16
static const int GEMM_SMEM = 3 * STG16 * (int)sizeof(uint16_t);  // 46080 B

template<int MODE>
__global__ void __launch_bounds__(256, 4) gemm_f16(const __half* __restrict__ A,
                                                   const __half* __restrict__ Bh,
                                                   const float* __restrict__ bias,
                                                   float* __restrict__ out) {
    extern __shared__ __align__(16) uint16_t sm16[];
    const int tid  = threadIdx.x;
    const int lane = tid & 31, wid = tid >> 5;
    const int wm = wid >> 1, wn = wid & 1;          // 4m x 2n warps
    const int m0 = blockIdx.y * 128, n0 = blockIdx.x * 64;

    const uint32_t sm_base = (uint32_t)__cvta_generic_to_shared(sm16);

    // A loader: row = tid>>1 (0..127), k-half = (tid&1)*16 (two cp16)
    const int arow = tid >> 1;
    const int akh = (tid & 1) * 16;
    const __half* pA = A + (size_t)(m0 + arow) * 1024 + akh;
    const uint32_t adst = (uint32_t)(arow * ROWP + akh) * 2;
    // B loader: row = tid>>2 (0..63), chunk = (tid&3)*8 (one cp16)
    const int brow = tid >> 2;
    const int bc = (tid & 3) * 8;
    const __half* pB = Bh + (size_t)(n0 + brow) * 1024 + bc;
    const uint32_t bdst = (uint32_t)(PLANEA + brow * ROWP + bc) * 2;

    auto issue = [&](int stage, int k0) {
        const uint32_t sb = sm_base + (uint32_t)stage * STG16 * 2;
        cp16(sb + adst,      pA + k0);
        cp16(sb + adst + 16, pA + k0 + 8);
        cp16(sb + bdst,      pB + k0);
        CP_COMMIT();
    };

    float acc[2][4][4];
    #pragma unroll
    for (int mt = 0; mt < 2; mt++)
        #pragma unroll
        for (int nt = 0; nt < 4; nt++)
            #pragma unroll
            for (int e = 0; e < 4; e++) acc[mt][nt][e] = 0.0f;

    const int lrow = lane & 15, lcol = (lane >> 4) * 8;

    issue(0, 0);
    issue(1, 32);

    for (int it = 0; it < 32; it++) {
        if (it < 31) asm volatile("cp.async.wait_group 1;");
        else         asm volatile("cp.async.wait_group 0;");
        __syncthreads();

        const int s = it - (it / 3) * 3;    // it % 3
        const uint32_t base_a = sm_base + (uint32_t)(s * STG16) * 2;
        const uint32_t base_b = base_a + (uint32_t)PLANEA * 2;

        #pragma unroll
        for (int ks = 0; ks < 2; ks++) {
            const uint32_t ko = (uint32_t)(ks * 16 + lcol) * 2;

            uint32_t bhi[4][2];
            #pragma unroll
            for (int j = 0; j < 2; j++) {
                const uint32_t off = (uint32_t)((wn*32 + j*16 + lrow) * ROWP) * 2 + ko;
                uint32_t r0, r1, r2, r3;
                LDSM4(r0, r1, r2, r3, base_b + off);
                bhi[2*j][0] = r0; bhi[2*j][1] = r2;
                bhi[2*j+1][0] = r1; bhi[2*j+1][1] = r3;
            }

            uint32_t af[2][4];
            #pragma unroll
            for (int mt = 0; mt < 2; mt++) {
                const uint32_t off = (uint32_t)((wm*32 + mt*16 + lrow) * ROWP) * 2 + ko;
                LDSM4(af[mt][0], af[mt][1], af[mt][2], af[mt][3], base_a + off);
            }
            #pragma unroll
            for (int mt = 0; mt < 2; mt++)
                #pragma unroll
                for (int nt = 0; nt < 4; nt++)
                    MMA_F16(acc[mt][nt], af[mt], bhi[nt]);
        }

        if (it + 2 < 32) {
            const int ns = (it + 2) - ((it + 2) / 3) * 3;
            issue(ns, (it + 2) * 32);
        }
    }

    const int gid = lane >> 2, tig = lane & 3;
    #pragma unroll
    for (int mt = 0; mt < 2; mt++)
        #pragma unroll
        for (int nt = 0; nt < 4; nt++) {
            const int mr = m0 + wm*32 + mt*16 + gid;
            const int nc = n0 + wn*32 + nt*8 + 2*tig;
            emit<MODE>(mr,     nc,     acc[mt][nt][0], bias, out);
            emit<MODE>(mr,     nc + 1, acc[mt][nt][1], bias, out);
            emit<MODE>(mr + 8, nc,     acc[mt][nt][2], bias, out);
            emit<MODE>(mr + 8, nc + 1, acc[mt][nt][3], bias, out);
        }
}

// ---------------------------------------------------------------------------
// Flash attention, fp16 rounded operands (fp32 softmax/accum);
// KV-stage 128 (two 64-halves per stage). grid (T/128, NBH), 256 threads.
// (unchanged from round 10 — verified)
// ---------------------------------------------------------------------------
#define KVP 72
#define PLH (64*KVP)                            // fp16 per half-plane
#define PLHB (PLH*2)                            // bytes per half-plane
#define STAGEB (4*PLHB)                         // K0,K1,V0,V1
static const int ATTN_SMEM = 2 * STAGEB;        // 73728 B

__global__ void __launch_bounds__(256) attn_mma() {
    extern __shared__ __align__(16) uint16_t asm16[];
    const int tid  = threadIdx.x;
    const int lane = tid & 31, w = tid >> 5;
    const int gid  = lane >> 2, qc = lane & 3;
    const int lrow = lane & 15, lhalf = (lane >> 4);
    const int qi = gridDim.x - 1 - blockIdx.x;   // heavy tiles first
    const int bh = blockIdx.y;

    const uint32_t smb = (uint32_t)__cvta_generic_to_shared(asm16);

    const __half* Khg = g_Kh  + (size_t)bh * T_ * HD_;
    const __half* Vhg = g_Vth + (size_t)bh * HD_ * T_;

    const int lr = tid >> 2, c4 = tid & 3;
    auto issue = [&](int st, int stIdx) {
        const uint32_t sb = smb + (uint32_t)st * STAGEB;
        const int kv0 = stIdx * 128;
        #pragma unroll
        for (int h = 0; h < 2; h++) {
            const __half* kh = Khg + ((size_t)(kv0 + h*64) + lr) * 64;
            const __half* vh = Vhg + (size_t)lr * T_ + kv0 + h*64;
            const uint32_t kpl = sb + (uint32_t)h * PLHB;
            const uint32_t vpl = sb + (uint32_t)(2 + h) * PLHB;
            #pragma unroll
            for (int u = 0; u < 2; u++) {
                const int c = c4 + 4*u;
                const uint32_t d = (uint32_t)(lr*KVP + c*8) * 2;
                cp16(kpl + d, kh + c*8);
                cp16(vpl + d, vh + c*8);
            }
        }
        CP_COMMIT();
    };

    issue(0, 0);

    // Q fragments (persistent, rounded fp16 loaded directly as packed pairs)
    uint32_t qh[4][4];
    {
        const size_t qb = ((size_t)bh * T_ + qi*128 + w*16) * HD_;
        #pragma unroll
        for (int ks = 0; ks < 4; ks++)
            #pragma unroll
            for (int kh = 0; kh < 2; kh++)
                #pragma unroll
                for (int h2 = 0; h2 < 2; h2++) {
                    const size_t off = qb + (size_t)(gid + 8*h2)*HD_ + ks*16 + kh*8 + 2*qc;
                    qh[ks][h2 + 2*kh] = *(const uint32_t*)(g_Qh + off);
                }
    }

    float m0 = -1e30f, m1 = -1e30f, l0 = 0.0f, l1 = 0.0f;
    float oacc[8][4];
    #pragma unroll
    for (int dt = 0; dt < 8; dt++)
        #pragma unroll
        for (int e = 0; e < 4; e++) oacc[dt][e] = 0.0f;

    const int r0 = qi*128 + w*16 + gid;
    const int r1 = r0 + 8;
    const uint32_t lbase = (uint32_t)(lrow*KVP + lhalf*8) * 2;

    for (int st = 0; st <= qi; st++) {
        if (st + 1 <= qi) issue((st + 1) & 1, st + 1);
        if (st + 1 <= qi) asm volatile("cp.async.wait_group 1;");
        else              asm volatile("cp.async.wait_group 0;");
        __syncthreads();

        const uint32_t sb = smb + (uint32_t)(st & 1) * STAGEB;

        #pragma unroll
        for (int h = 0; h < 2; h++) {
            const int kt = 2*st + h;
            const uint32_t kbh = sb + (uint32_t)h * PLHB;
            const uint32_t vbh = sb + (uint32_t)(2 + h) * PLHB;

            // ---- S = Q K^T ----
            float sacc[8][4];
            #pragma unroll
            for (int nt = 0; nt < 8; nt++)
                #pragma unroll
                for (int e = 0; e < 4; e++) sacc[nt][e] = 0.0f;

            #pragma unroll
            for (int ks = 0; ks < 4; ks++) {
                #pragma unroll
                for (int np = 0; np < 4; np++) {
                    const uint32_t off = lbase + (uint32_t)(np*16*KVP + ks*16) * 2;
                    uint32_t h0, h1, h2, h3;
                    LDSM4(h0, h1, h2, h3, kbh + off);
                    uint32_t ba[2] = {h0, h2}, bb[2] = {h1, h3};
                    MMA_F16(sacc[2*np],   qh[ks], ba);
                    MMA_F16(sacc[2*np+1], qh[ks], bb);
                }
            }

            // ---- causal mask on diagonal tiles ----
            if (kt >= 2*qi) {
                #pragma unroll
                for (int nt = 0; nt < 8; nt++) {
                    const int c0 = kt*64 + nt*8 + 2*qc;
                    if (c0     > r0) sacc[nt][0] = -1e30f;
                    if (c0 + 1 > r0) sacc[nt][1] = -1e30f;
                    if (c0     > r1) sacc[nt][2] = -1e30f;
                    if (c0 + 1 > r1) sacc[nt][3] = -1e30f;
                }
            }

            // ---- online softmax (rows r0, r1; quad-local reduction) ----
            float rm0 = -1e30f, rm1 = -1e30f;
            #pragma unroll
            for (int nt = 0; nt < 8; nt++) {
                rm0 = fmaxf(rm0, fmaxf(sacc[nt][0], sacc[nt][1]));
                rm1 = fmaxf(rm1, fmaxf(sacc[nt][2], sacc[nt][3]));
            }
            rm0 = fmaxf(rm0, __shfl_xor_sync(0xffffffffu, rm0, 1));
            rm0 = fmaxf(rm0, __shfl_xor_sync(0xffffffffu, rm0, 2));
            rm1 = fmaxf(rm1, __shfl_xor_sync(0xffffffffu, rm1, 1));
            rm1 = fmaxf(rm1, __shfl_xor_sync(0xffffffffu, rm1, 2));
            const float mn0 = fmaxf(m0, rm0), mn1 = fmaxf(m1, rm1);
            const float cr0 = __expf(m0 - mn0), cr1 = __expf(m1 - mn1);
            m0 = mn0; m1 = mn1;
            float s0 = 0.0f, s1 = 0.0f;
            #pragma unroll
            for (int nt = 0; nt < 8; nt++) {
                sacc[nt][0] = __expf(sacc[nt][0] - mn0); s0 += sacc[nt][0];
                sacc[nt][1] = __expf(sacc[nt][1] - mn0); s0 += sacc[nt][1];
                sacc[nt][2] = __expf(sacc[nt][2] - mn1); s1 += sacc[nt][2];
                sacc[nt][3] = __expf(sacc[nt][3] - mn1); s1 += sacc[nt][3];
            }
            s0 += __shfl_xor_sync(0xffffffffu, s0, 1);
            s0 += __shfl_xor_sync(0xffffffffu, s0, 2);
            s1 += __shfl_xor_sync(0xffffffffu, s1, 1);
            s1 += __shfl_xor_sync(0xffffffffu, s1, 2);
            l0 = l0 * cr0 + s0;
            l1 = l1 * cr1 + s1;
            #pragma unroll
            for (int dt = 0; dt < 8; dt++) {
                oacc[dt][0] *= cr0; oacc[dt][1] *= cr0;
                oacc[dt][2] *= cr1; oacc[dt][3] *= cr1;
            }

            // ---- O += P V (P rounded in-register) ----
            #pragma unroll
            for (int kpv = 0; kpv < 4; kpv++) {
                uint32_t pa[4];
                pa[0] = pack2h(sacc[2*kpv][0],   sacc[2*kpv][1]);
                pa[1] = pack2h(sacc[2*kpv][2],   sacc[2*kpv][3]);
                pa[2] = pack2h(sacc[2*kpv+1][0], sacc[2*kpv+1][1]);
                pa[3] = pack2h(sacc[2*kpv+1][2], sacc[2*kpv+1][3]);
                #pragma unroll
                for (int np = 0; np < 4; np++) {
                    const uint32_t off = lbase + (uint32_t)(np*16*KVP + kpv*16) * 2;
                    uint32_t h0, h1, h2, h3;
                    LDSM4(h0, h1, h2, h3, vbh + off);
                    uint32_t va[2] = {h0, h2}, vb[2] = {h1, h3};
                    MMA_F16(oacc[2*np],   pa, va);
                    MMA_F16(oacc[2*np+1], pa, vb);
                }
            }
        }
        __syncthreads();   // stage reads complete before next overwrite
    }

    // ---- epilogue: write Y rounded for the proj GEMM ----
    const int b = bh >> 4, h = bh & 15;
    const float inv0 = 1.0f / l0, inv1 = 1.0f / l1;
    const size_t y0 = ((size_t)(b * T_ + r0)) * C_ + h * HD_;
    const size_t y1 = ((size_t)(b * T_ + r1)) * C_ + h * HD_;
    #pragma unroll
    for (int dt = 0; dt < 8; dt++) {
        const int d = dt*8 + 2*qc;
        *(uint32_t*)(g_yh + y0 + d) = pack2h(oacc[dt][0] * inv0, oacc[dt][1] * inv0);
        *(uint32_t*)(g_yh + y1 + d) = pack2h(oacc[dt][2] * inv1, oacc[dt][3] * inv1);
    }
}

extern "C" void kernel_launch(void* const* d_in, const int* in_sizes, int n_in,
                              void* d_out, int out_size) {
    const float* x      = (const float*)d_in[0];
    const float* W_attn = (const float*)d_in[1];
    const float* b_attn = (const float*)d_in[2];
    const float* W_proj = (const float*)d_in[3];
    const float* b_proj = (const float*)d_in[4];
    float* out = (float*)d_out;

    cudaFuncSetAttribute(gemm_f16<0>, cudaFuncAttributeMaxDynamicSharedMemorySize, GEMM_SMEM);
    cudaFuncSetAttribute(gemm_f16<1>, cudaFuncAttributeMaxDynamicSharedMemorySize, GEMM_SMEM);
    cudaFuncSetAttribute(attn_mma,    cudaFuncAttributeMaxDynamicSharedMemorySize, ATTN_SMEM);

    __half *xh, *yh, *wah, *wph;
    cudaGetSymbolAddress((void**)&xh,  g_xh);  cudaGetSymbolAddress((void**)&yh,  g_yh);
    cudaGetSymbolAddress((void**)&wah, g_wah); cudaGetSymbolAddress((void**)&wph, g_wph);

    // converters
    round_f4<<<(M_*C_/4)/256, 256>>>(x, xh);
    round_wt<3*C_><<<dim3(3*C_/32, C_/32), 256>>>(W_attn, wah);
    round_wt<C_><<<dim3(C_/32, C_/32), 256>>>(W_proj, wph);

    // qkv (epilogue rounds Q (pre-scaled), K, transposed V)
    gemm_f16<0><<<dim3(3*C_/64, M_/128), 256, GEMM_SMEM>>>(xh, wah, b_attn, nullptr);
    // attention (epilogue rounds Y)
    attn_mma<<<dim3(T_/128, NBH_), 256, ATTN_SMEM>>>();
    // proj
    gemm_f16<1><<<dim3(C_/64, M_/128), 256, GEMM_SMEM>>>(yh, wph, b_proj, out);
}